// round 13
// baseline (speedup 1.0000x reference)
#include <cuda_runtime.h>
#include <math.h>

#define Bsz 8
#define Lseq 2048
#define INF 64
#define OUTF 64
#define Hd 128
#define Nst 64
#define NLAY 4
#define L2 4096
#define ROWS (Bsz*Lseq)

typedef unsigned long long ull;

// ---------------- persistent scratch ----------------
__device__ float  g_h  [ROWS*Hd];          // activations (B,L,H)
__device__ float  g_hnT[Bsz*Hd*Lseq];      // layernormed, transposed (B,H,L)
__device__ float  g_yT [Bsz*Hd*Lseq];      // gelu(conv output), transposed (B,H,L)
__device__ float4 g_KdP[NLAY*(Hd/2)*Lseq]; // spectra f<2048, channel pairs interleaved (K1,K2)
__device__ float2 g_KdN[NLAY*Hd];          // spectrum bin 2048 per channel
__device__ float2 g_tw [L2/2];             // twiddles W_4096^m, m < 2048
__device__ float  g_w1T[NLAY*Hd*Hd];       // transposed weights [k][c]
__device__ float  g_w2T[NLAY*Hd*Hd];
__device__ float  g_encWT[INF*Hd];
__device__ float  g_decWT[Hd*OUTF];

__device__ __forceinline__ float2 cmulf(float2 a, float2 b) {
    return make_float2(a.x*b.x - a.y*b.y, a.x*b.y + a.y*b.x);
}
__device__ __forceinline__ float2 caddf(float2 a, float2 b){ return make_float2(a.x+b.x, a.y+b.y); }
__device__ __forceinline__ float2 csubf(float2 a, float2 b){ return make_float2(a.x-b.x, a.y-b.y); }
// a + sgn*i*d
__device__ __forceinline__ float2 addi(float2 a, float2 d, float sgn) {
    return make_float2(a.x - sgn*d.y, a.y + sgn*d.x);
}
// ---- packed f32x2 helpers ----
__device__ __forceinline__ ull pk(float x, float y) {
    ull r; asm("mov.b64 %0, {%1, %2};" : "=l"(r) : "f"(x), "f"(y)); return r;
}
__device__ __forceinline__ void upk(ull p, float& x, float& y) {
    asm("mov.b64 {%0, %1}, %2;" : "=f"(x), "=f"(y) : "l"(p));
}
__device__ __forceinline__ ull ffma2(ull a, ull b, ull c) {
    ull d; asm("fma.rn.f32x2 %0, %1, %2, %3;" : "=l"(d) : "l"(a), "l"(b), "l"(c)); return d;
}

// ---------------- prep: twiddles + weight transposes (one launch) ----------------
__global__ void prep_kernel(const float* __restrict__ enc_w, const float* __restrict__ dec_w,
                            const float* __restrict__ w1, const float* __restrict__ w2) {
    int tid = blockIdx.x * 256 + threadIdx.x;
    if (tid < L2/2) {
        float s, c;
        sincospif(-(float)tid / 2048.0f, &s, &c);
        g_tw[tid] = make_float2(c, s);
    }
    if (tid < INF*Hd) { int k = tid >> 7, c = tid & 127; g_encWT[tid] = enc_w[c*INF + k]; }
    if (tid < Hd*OUTF) { int k = tid >> 6, o = tid & 63; g_decWT[tid] = dec_w[o*Hd + k]; }
    if (tid < NLAY*Hd*Hd) {
        int lay = tid >> 14, r = tid & 16383, k = r >> 7, c = r & 127;
        g_w1T[tid] = w1[lay*Hd*Hd + c*Hd + k];
        g_w2T[tid] = w2[lay*Hd*Hd + c*Hd + k];
    }
}

// ---------------- radix-8 butterfly (DIT-style: twiddles applied to inputs) ----------------
__device__ __forceinline__ void radix8(const float2 u[8],
                                       float2 w1, float2 w2, float2 w3, float2 w4,
                                       float sgnF, float2 out[8]) {
    const float cc = 0.70710678118654752f;
    float2 w5 = cmulf(w4, w1);
    float2 w6 = cmulf(w3, w3);
    float2 w7 = cmulf(w4, w3);
    float2 t0 = u[0];
    float2 t1 = cmulf(w1, u[1]);
    float2 t2 = cmulf(w2, u[2]);
    float2 t3 = cmulf(w3, u[3]);
    float2 t4 = cmulf(w4, u[4]);
    float2 t5 = cmulf(w5, u[5]);
    float2 t6 = cmulf(w6, u[6]);
    float2 t7 = cmulf(w7, u[7]);
    float2 s04 = caddf(t0, t4), d04 = csubf(t0, t4);
    float2 s26 = caddf(t2, t6), d26 = csubf(t2, t6);
    float2 s15 = caddf(t1, t5), d15 = csubf(t1, t5);
    float2 s37 = caddf(t3, t7), d37 = csubf(t3, t7);
    float2 E0 = caddf(s04, s26), E2 = csubf(s04, s26);
    float2 E1 = addi(d04, d26, sgnF), E3 = addi(d04, d26, -sgnF);
    float2 O0 = caddf(s15, s37), O2 = csubf(s15, s37);
    float2 O1 = addi(d15, d37, sgnF), O3 = addi(d15, d37, -sgnF);
    float2 W81 = make_float2(cc,  sgnF*cc);
    float2 W83 = make_float2(-cc, sgnF*cc);
    float2 p1 = cmulf(O1, W81);
    float2 p2 = make_float2(-sgnF*O2.y, sgnF*O2.x);   // sgnF * i * O2
    float2 p3 = cmulf(O3, W83);
    out[0] = caddf(E0, O0); out[4] = csubf(E0, O0);
    out[1] = caddf(E1, p1); out[5] = csubf(E1, p1);
    out[2] = caddf(E2, p2); out[6] = csubf(E2, p2);
    out[3] = caddf(E3, p3); out[7] = csubf(E3, p3);
}

// ---------------- 2048-pt Stockham FFT: radix-4 then 3x radix-8 (result in `a`) ----------------
__device__ float2* fft2048_m(float2* a, float2* b, bool inverse) {
    float2* src = a; float2* dst = b;
    const float sgnF = inverse ? 1.0f : -1.0f;
    __syncthreads();
    for (int j = threadIdx.x; j < 512; j += blockDim.x) {
        float2 u0 = src[j], u1 = src[j+512], u2 = src[j+1024], u3 = src[j+1536];
        float2 a02 = caddf(u0, u2), s02 = csubf(u0, u2);
        float2 a13 = caddf(u1, u3), s13 = csubf(u1, u3);
        int o = j << 2;
        dst[o  ] = caddf(a02, a13);
        dst[o+1] = addi(s02, s13, sgnF);
        dst[o+2] = csubf(a02, a13);
        dst[o+3] = addi(s02, s13, -sgnF);
    }
    { float2* tmp = src; src = dst; dst = tmp; }
    int L = 4, mult = 128;
    #pragma unroll
    for (int t = 0; t < 3; t++) {
        __syncthreads();
        for (int j = threadIdx.x; j < 256; j += blockDim.x) {
            int k = j & (L - 1);
            int blk = j >> (2 + 3*t);
            float2 u[8];
            #pragma unroll
            for (int i = 0; i < 8; i++) u[i] = src[j + i*256];
            int idx = k * mult;
            float2 w1 = g_tw[idx], w2 = g_tw[2*idx], w3 = g_tw[3*idx], w4 = g_tw[4*idx];
            if (inverse) { w1.y = -w1.y; w2.y = -w2.y; w3.y = -w3.y; w4.y = -w4.y; }
            float2 o8[8];
            radix8(u, w1, w2, w3, w4, sgnF, o8);
            int o = (blk << 3)*L + k;
            #pragma unroll
            for (int i = 0; i < 8; i++) dst[o + i*L] = o8[i];
        }
        { float2* tmp = src; src = dst; dst = tmp; }
        L <<= 3; mult >>= 3;
    }
    __syncthreads();
    return src;
}

// ---------------- vectorized in-place radix-8 stage (adjacent-pair, LDS.128/STS.128) ----------------
// 256 threads, thread owns j0=2*tid and j0+1. Valid for L in {8,64,512} (k0 even, same blk).
__device__ __forceinline__ void stage_v(float2* A, int t, int L, int mult,
                                        float sgnF, bool conj) {
    int j0 = threadIdx.x << 1;
    float2 u[2][8];
    #pragma unroll
    for (int i = 0; i < 8; i++) {
        float4 v = *(const float4*)&A[j0 + i*512];
        u[0][i] = make_float2(v.x, v.y);
        u[1][i] = make_float2(v.z, v.w);
    }
    __syncthreads();
    int k0 = j0 & (L - 1);
    int blkq = j0 >> (3*t);
    float2 o8a[8], o8b[8];
    {
        int idx = k0 * mult;
        float2 w1 = g_tw[idx], w2 = g_tw[2*idx], w3 = g_tw[3*idx], w4 = g_tw[4*idx];
        if (conj) { w1.y = -w1.y; w2.y = -w2.y; w3.y = -w3.y; w4.y = -w4.y; }
        radix8(u[0], w1, w2, w3, w4, sgnF, o8a);
    }
    {
        int idx = (k0 + 1) * mult;
        float2 w1 = g_tw[idx], w2 = g_tw[2*idx], w3 = g_tw[3*idx], w4 = g_tw[4*idx];
        if (conj) { w1.y = -w1.y; w2.y = -w2.y; w3.y = -w3.y; w4.y = -w4.y; }
        radix8(u[1], w1, w2, w3, w4, sgnF, o8b);
    }
    int o = (blkq << (3*t + 3)) + k0;
    #pragma unroll
    for (int i = 0; i < 8; i++)
        *(float4*)&A[o + i*L] = make_float4(o8a[i].x, o8a[i].y, o8b[i].x, o8b[i].y);
    __syncthreads();
}

// ---------------- FFT causal conv, in-place vectorized (32 KB smem) ----------------
__global__ __launch_bounds__(256, 4) void conv_kernel(const float* __restrict__ dvec, int lay) {
    __shared__ __align__(16) float2 A[L2];
    int blk = blockIdx.x;
    int b = blk >> 6, hp = blk & 63;
    int h0 = 2*hp;
    int tid = threadIdx.x;
    const float* u1 = g_hnT + ((size_t)b*Hd + h0)*Lseq;
    const float* u2 = u1 + Lseq;
    const float2 ONE = make_float2(1.f, 0.f);
    int j0 = tid << 1;

    // forward stage 0 (L=1, twiddles=1): global (pair loads) -> butterflies -> A (paired stores)
    {
        float2 u[2][8], o8a[8], o8b[8];
        #pragma unroll
        for (int i = 0; i < 4; i++) {
            float2 a1 = *(const float2*)&u1[j0 + i*512];
            float2 a2 = *(const float2*)&u2[j0 + i*512];
            u[0][i] = make_float2(a1.x, a2.x);
            u[1][i] = make_float2(a1.y, a2.y);
        }
        #pragma unroll
        for (int i = 4; i < 8; i++) { u[0][i] = make_float2(0.f,0.f); u[1][i] = make_float2(0.f,0.f); }
        radix8(u[0], ONE, ONE, ONE, ONE, -1.0f, o8a);
        radix8(u[1], ONE, ONE, ONE, ONE, -1.0f, o8b);
        // outputs: a -> A[8*j0 + i] = A[16*tid + i]; b -> A[16*tid + 8 + i]
        #pragma unroll
        for (int i = 0; i < 8; i += 2)
            *(float4*)&A[(tid << 4) + i] = make_float4(o8a[i].x, o8a[i].y, o8a[i+1].x, o8a[i+1].y);
        #pragma unroll
        for (int i = 0; i < 8; i += 2)
            *(float4*)&A[(tid << 4) + 8 + i] = make_float4(o8b[i].x, o8b[i].y, o8b[i+1].x, o8b[i+1].y);
    }
    __syncthreads();
    // forward stages 1..3 (vectorized)
    stage_v(A, 1, 8,   64, -1.0f, false);
    stage_v(A, 2, 64,  8,  -1.0f, false);
    stage_v(A, 3, 512, 1,  -1.0f, false);

    // pointwise using K-real symmetry, adjacent pairs (f0, f0+1), f0 even
    const float4* KP = g_KdP + ((size_t)lay*(Hd/2) + hp)*Lseq;
    #pragma unroll
    for (int s = 0; s < 4; s++) {
        int f0 = j0 + s*512;               // even, 0..2046
        int fr0 = (L2 - f0) & (L2-1);      // even
        float4 zp = *(const float4*)&A[f0];            // zf(f0), zf(f0+1)
        float2 zf0 = make_float2(zp.x, zp.y);
        float2 zf1 = make_float2(zp.z, zp.w);
        float2 zr0 = A[fr0];
        float2 zr1 = A[fr0 - 1 >= 0 ? ((fr0 - 1) & (L2-1)) : 0];  // fr for f0+1 = fr0-1 (f0>0); f0=0 -> 4095
        if (f0 == 0) zr1 = A[4095];
        float4 K0 = KP[f0];
        float4 K1v = KP[f0 + 1];
        float2 Y10, Y20, Y11, Y21;
        {
            float2 K1 = make_float2(K0.x, K0.y), K2 = make_float2(K0.z, K0.w);
            float2 U1 = make_float2(0.5f*(zf0.x + zr0.x),  0.5f*(zf0.y - zr0.y));
            float2 U2 = make_float2(0.5f*(zf0.y + zr0.y), -0.5f*(zf0.x - zr0.x));
            Y10 = cmulf(U1, K1); Y20 = cmulf(U2, K2);
        }
        {
            float2 K1 = make_float2(K1v.x, K1v.y), K2 = make_float2(K1v.z, K1v.w);
            float2 U1 = make_float2(0.5f*(zf1.x + zr1.x),  0.5f*(zf1.y - zr1.y));
            float2 U2 = make_float2(0.5f*(zf1.y + zr1.y), -0.5f*(zf1.x - zr1.x));
            Y11 = cmulf(U1, K1); Y21 = cmulf(U2, K2);
        }
        *(float4*)&A[f0] = make_float4(Y10.x - Y20.y, Y10.y + Y20.x,
                                       Y11.x - Y21.y, Y11.y + Y21.x);
        // mirror writes: conj(Y1) + i*conj(Y2)
        if (f0 != 0) {
            A[fr0]     = make_float2(Y10.x + Y20.y, Y20.x - Y10.y);
            A[fr0 - 1] = make_float2(Y11.x + Y21.y, Y21.x - Y11.y);
        } else {
            A[4095] = make_float2(Y11.x + Y21.y, Y21.x - Y11.y);
            // self-paired Nyquist bin 2048
            float2 z = A[2048];
            float2 K1n = g_KdN[lay*Hd + h0];
            float2 K2n = g_KdN[lay*Hd + h0 + 1];
            float2 Y1n = make_float2(z.x*K1n.x, z.x*K1n.y);
            float2 Y2n = make_float2(z.y*K2n.x, z.y*K2n.y);
            A[2048] = make_float2(Y1n.x - Y2n.y, Y1n.y + Y2n.x);
        }
    }
    __syncthreads();

    // inverse stage 0 (L=1, twiddles=1), vectorized
    {
        float2 u[2][8];
        #pragma unroll
        for (int i = 0; i < 8; i++) {
            float4 v = *(const float4*)&A[j0 + i*512];
            u[0][i] = make_float2(v.x, v.y);
            u[1][i] = make_float2(v.z, v.w);
        }
        __syncthreads();
        float2 o8a[8], o8b[8];
        radix8(u[0], ONE, ONE, ONE, ONE, 1.0f, o8a);
        radix8(u[1], ONE, ONE, ONE, ONE, 1.0f, o8b);
        #pragma unroll
        for (int i = 0; i < 8; i += 2)
            *(float4*)&A[(tid << 4) + i] = make_float4(o8a[i].x, o8a[i].y, o8a[i+1].x, o8a[i+1].y);
        #pragma unroll
        for (int i = 0; i < 8; i += 2)
            *(float4*)&A[(tid << 4) + 8 + i] = make_float4(o8b[i].x, o8b[i].y, o8b[i+1].x, o8b[i+1].y);
        __syncthreads();
    }
    stage_v(A, 1, 8,  64, 1.0f, true);
    stage_v(A, 2, 64, 8,  1.0f, true);
    // inverse stage 3 fused with epilogue: keep only l < 2048, paired global stores
    {
        float d1 = dvec[h0], d2 = dvec[h0+1];
        float* y1 = g_yT + ((size_t)b*Hd + h0)*Lseq;
        float* y2 = y1 + Lseq;
        float2 u[2][8];
        #pragma unroll
        for (int i = 0; i < 8; i++) {
            float4 v = *(const float4*)&A[j0 + i*512];
            u[0][i] = make_float2(v.x, v.y);
            u[1][i] = make_float2(v.z, v.w);
        }
        // no smem writes follow -> no barrier needed
        float2 o8a[8], o8b[8];
        {
            int idx = j0;   // k=j0, mult=1
            float2 w1 = g_tw[idx], w2 = g_tw[2*idx], w3 = g_tw[3*idx], w4 = g_tw[4*idx];
            w1.y = -w1.y; w2.y = -w2.y; w3.y = -w3.y; w4.y = -w4.y;
            radix8(u[0], w1, w2, w3, w4, 1.0f, o8a);
        }
        {
            int idx = j0 + 1;
            float2 w1 = g_tw[idx], w2 = g_tw[2*idx], w3 = g_tw[3*idx], w4 = g_tw[4*idx];
            w1.y = -w1.y; w2.y = -w2.y; w3.y = -w3.y; w4.y = -w4.y;
            radix8(u[1], w1, w2, w3, w4, 1.0f, o8b);
        }
        #pragma unroll
        for (int i = 0; i < 4; i++) {
            int l = j0 + i*512;
            float va1 = o8a[i].x*(1.0f/L2) + u1[l]*d1;
            float vb1 = o8b[i].x*(1.0f/L2) + u1[l+1]*d1;
            float va2 = o8a[i].y*(1.0f/L2) + u2[l]*d2;
            float vb2 = o8b[i].y*(1.0f/L2) + u2[l+1]*d2;
            float ta1 = 0.7978845608028654f * (va1 + 0.044715f * va1*va1*va1);
            float tb1 = 0.7978845608028654f * (vb1 + 0.044715f * vb1*vb1*vb1);
            float ta2 = 0.7978845608028654f * (va2 + 0.044715f * va2*va2*va2);
            float tb2 = 0.7978845608028654f * (vb2 + 0.044715f * vb2*vb2*vb2);
            *(float2*)&y1[l] = make_float2(0.5f*va1*(1.0f + tanhf(ta1)),
                                           0.5f*vb1*(1.0f + tanhf(tb1)));
            *(float2*)&y2[l] = make_float2(0.5f*va2*(1.0f + tanhf(ta2)),
                                           0.5f*vb2*(1.0f + tanhf(tb2)));
        }
    }
}

// ---------------- encoder GEMM (f32x2 row-pairs) + fused layer-0 LN -> g_h, g_hnT ----------------
__global__ __launch_bounds__(256) void encoder_kernel(const float* __restrict__ x,
                                                      const float* __restrict__ eb,
                                                      const float* __restrict__ nw,
                                                      const float* __restrict__ nb) {
    __shared__ float xs[32][INF];     // staged input rows
    __shared__ ull   zs2[INF][17];    // packed row-pairs (pad 17 to break bank conflicts)
    __shared__ float tile[32][129];   // h rows for LN
    int row0 = blockIdx.x * 32;
    int b = row0 >> 11, l0 = row0 & 2047;
    int tid = threadIdx.x;
    for (int idx = tid; idx < 32*INF; idx += 256)
        xs[idx >> 6][idx & 63] = x[(size_t)(row0 + (idx >> 6))*INF + (idx & 63)];
    __syncthreads();
    for (int idx = tid; idx < INF*16; idx += 256) {
        int p = idx >> 6, k = idx & 63;
        zs2[k][p] = pk(xs[2*p][k], xs[2*p+1][k]);
    }
    __syncthreads();
    int c = tid & 127, half = tid >> 7;
    int p0 = half * 8;
    ull acc[8];
    {
        float bv = eb[c];
        ull bp = pk(bv, bv);
        #pragma unroll
        for (int p = 0; p < 8; p++) acc[p] = bp;
    }
    #pragma unroll 4
    for (int k = 0; k < INF; k++) {
        float wv = g_encWT[k*Hd + c];
        ull wp = pk(wv, wv);
        #pragma unroll
        for (int p = 0; p < 8; p++) acc[p] = ffma2(zs2[k][p0 + p], wp, acc[p]);
    }
    #pragma unroll
    for (int p = 0; p < 8; p++) {
        float h0v, h1v;
        upk(acc[p], h0v, h1v);
        int ra = 2*(p0 + p), rb = ra + 1;
        g_h[(size_t)(row0 + ra)*Hd + c] = h0v;
        g_h[(size_t)(row0 + rb)*Hd + c] = h1v;
        tile[ra][c] = h0v; tile[rb][c] = h1v;
    }
    __syncthreads();
    int warp = tid >> 5, lane = tid & 31;
    #pragma unroll
    for (int rr = 0; rr < 4; rr++) {
        int l = warp*4 + rr;
        float v[4]; float sum = 0.f;
        #pragma unroll
        for (int i = 0; i < 4; i++) { v[i] = tile[l][lane + 32*i]; sum += v[i]; }
        #pragma unroll
        for (int o = 16; o; o >>= 1) sum += __shfl_xor_sync(0xffffffffu, sum, o);
        float mu = sum * (1.0f/Hd);
        float var = 0.f;
        #pragma unroll
        for (int i = 0; i < 4; i++) { float t = v[i]-mu; var += t*t; }
        #pragma unroll
        for (int o = 16; o; o >>= 1) var += __shfl_xor_sync(0xffffffffu, var, o);
        float rstd = rsqrtf(var * (1.0f/Hd) + 1e-5f);
        #pragma unroll
        for (int i = 0; i < 4; i++) {
            int cc = lane + 32*i;
            tile[l][cc] = (v[i]-mu)*rstd*nw[cc] + nb[cc];
        }
    }
    __syncthreads();
    for (int idx = tid; idx < 32*Hd; idx += 256) {
        int hh = idx >> 5, l = idx & 31;
        g_hnT[((size_t)(b*Hd + hh))*Lseq + l0 + l] = tile[l][hh];
    }
}

// ---------------- FUSED cauchy + kernel-spectrum (symmetric storage), batched over layers ----------------
__global__ __launch_bounds__(512) void ckfft_kernel(
        const float* __restrict__ lre, const float* __restrict__ lim,
        const float* __restrict__ pre, const float* __restrict__ pim,
        const float* __restrict__ bre, const float* __restrict__ bim,
        const float* __restrict__ cre, const float* __restrict__ cim,
        const float* __restrict__ lstep) {
    extern __shared__ float2 sm[];
    float2* A  = sm;           // 2048
    float2* Bb = sm + Lseq;    // 2048
    __shared__ float2 slam[Nst];
    __shared__ ull sp[4][Nst][2];
    int h = blockIdx.x, lay = blockIdx.y;
    int hh = lay*Hd + h;
    int tid = threadIdx.x;
    if (tid < Nst) {
        int idx = hh*Nst + tid;
        slam[tid] = make_float2(lre[idx], lim[idx]);
        float2 P  = make_float2(pre[idx], pim[idx]);
        float2 Bv = make_float2(bre[idx], bim[idx]);
        float2 Cc = make_float2(cre[idx], -cim[idx]);
        float2 Pc = make_float2(P.x, -P.y);
        float2 vm[4];
        vm[0] = cmulf(Cc, Bv); vm[1] = cmulf(Cc, P);
        vm[2] = cmulf(Pc, Bv); vm[3] = cmulf(Pc, P);
        #pragma unroll
        for (int m = 0; m < 4; m++) {
            sp[m][tid][0] = pk(vm[m].x, vm[m].y);
            sp[m][tid][1] = pk(vm[m].y, -vm[m].x);
        }
    }
    __syncthreads();
    float ts = 2.0f / __expf(lstep[hh]);
    for (int l = tid; l < Lseq; l += 512) {
        // XLA-style omega (f32 angle + sincosf; l=L/2 must NOT be exactly -1)
        float ang = -6.2831853071795864f * ((float)l / (float)Lseq);
        float s, c;
        sincosf(ang, &s, &c);
        float dpx = 1.0f + c, dpy = s;
        float dmx = 1.0f - c, dmy = -s;
        float id2 = __fdividef(1.0f, dpx*dpx + dpy*dpy);
        float gx = ts * (dmx*dpx + dmy*dpy) * id2;
        float gy = ts * (dmy*dpx - dmx*dpy) * id2;
        float c2x = 2.0f*dpx*id2, c2y = -2.0f*dpy*id2;
        ull acc[4] = {0ull, 0ull, 0ull, 0ull};
        #pragma unroll 8
        for (int n = 0; n < Nst; n++) {
            float dx = gx - slam[n].x;
            float dy = gy - slam[n].y;
            float inv = __fdividef(1.0f, dx*dx + dy*dy);
            float rx = dx*inv, ryp = dy*inv;
            ull rxx = pk(rx, rx), ryy = pk(ryp, ryp);
            #pragma unroll
            for (int m = 0; m < 4; m++)
                acc[m] = ffma2(sp[m][n][0], rxx, ffma2(sp[m][n][1], ryy, acc[m]));
        }
        float k00x,k00y,k01x,k01y,k10x,k10y,k11x,k11y;
        upk(acc[0], k00x, k00y); upk(acc[1], k01x, k01y);
        upk(acc[2], k10x, k10y); upk(acc[3], k11x, k11y);
        float opx = 1.0f + k11x, opy = k11y;
        float oinv = __fdividef(1.0f, opx*opx + opy*opy);
        float wx = k01x*k10x - k01y*k10y;
        float wy = k01x*k10y + k01y*k10x;
        float cx = (wx*opx + wy*opy) * oinv;
        float cy = (wy*opx - wx*opy) * oinv;
        float rx2 = k00x - cx, ry2 = k00y - cy;
        A[l] = make_float2(c2x*rx2 - c2y*ry2, c2x*ry2 + c2y*rx2);
    }
    __syncthreads();
    // Kd storage: pair-interleaved float4 (slot h&1), f<2048 only; bin 2048 separate.
    float2* KP2 = (float2*)(g_KdP + ((size_t)lay*(Hd/2) + (h>>1))*Lseq);  // index 2*f + slot
    int slot = h & 1;
    // even bins from at (A) BEFORE the in-place IFFT destroys it
    for (int m = tid; m < Lseq; m += 512) {
        if (m < 1024) {
            float2 am = A[m];
            float2 ar = A[(Lseq - m) & (Lseq-1)];
            KP2[4*m + slot] = make_float2(0.5f*(am.x + ar.x), 0.5f*(am.y - ar.y));  // f=2m
        } else if (m == 1024) {
            g_KdN[hh] = make_float2(A[1024].x, 0.f);   // bin 2048
        }
    }
    float2* r = fft2048_m(A, Bb, true);
    for (int m = tid; m < Lseq; m += 512) {
        float xr = r[m].x * (1.0f/Lseq);
        float2 w = g_tw[m];
        Bb[m] = make_float2(xr * w.x, xr * w.y);
    }
    float2* r2 = fft2048_m(Bb, A, false);
    for (int m = tid; m < 1024; m += 512)
        KP2[4*m + 2 + slot] = r2[m];                   // f=2m+1
}

// ---------------- gated MLP + residual + fused next-layer LN (64 rows, 512 threads) ----------------
__global__ __launch_bounds__(512) void mlp_kernel(const float* __restrict__ b1,
                                                  const float* __restrict__ b2,
                                                  const float* __restrict__ nw,
                                                  const float* __restrict__ nb,
                                                  int lay, int do_ln) {
    const float* __restrict__ w1T = g_w1T + lay*Hd*Hd;
    const float* __restrict__ w2T = g_w2T + lay*Hd*Hd;
    // union: zs2 (32 KB, GEMM phase) then tile (33 KB, LN phase)
    __shared__ __align__(16) unsigned char smbuf[64*129*4];
    ull   (*zs2)[32]  = reinterpret_cast<ull(*)[32]>(smbuf);
    float (*tile)[129] = reinterpret_cast<float(*)[129]>(smbuf);
    int row0 = blockIdx.x * 64;
    int b = row0 >> 11, l0 = row0 & 2047;
    int tid = threadIdx.x;
    int c = tid & 127, grp = tid >> 7;   // 4 groups
    for (int idx = tid; idx < Hd*32; idx += 512) {
        int k = idx >> 5, p = idx & 31;
        float2 v = *(const float2*)&g_yT[((size_t)(b*Hd + k))*Lseq + l0 + 2*p];
        zs2[k][p] = pk(v.x, v.y);
    }
    __syncthreads();
    int p0 = grp * 8;
    ull acc1[8], acc2[8];
    {
        float b1v = b1[c], b2v = b2[c];
        ull p1 = pk(b1v, b1v), p2 = pk(b2v, b2v);
        #pragma unroll
        for (int p = 0; p < 8; p++) { acc1[p] = p1; acc2[p] = p2; }
    }
    #pragma unroll 2
    for (int k = 0; k < Hd; k++) {
        float w1v = w1T[k*Hd + c];
        float w2v = w2T[k*Hd + c];
        ull w1p = pk(w1v, w1v), w2p = pk(w2v, w2v);
        #pragma unroll
        for (int p = 0; p < 8; p++) {
            ull zp = zs2[k][p0 + p];
            acc1[p] = ffma2(zp, w1p, acc1[p]);
            acc2[p] = ffma2(zp, w2p, acc2[p]);
        }
    }
    __syncthreads();   // zs2 dead; tile may now alias it
    float hva[8], hvb[8];
    #pragma unroll
    for (int p = 0; p < 8; p++) {
        float o0, o1, g0, g1;
        upk(acc1[p], o0, o1);
        upk(acc2[p], g0, g1);
        int ra = 2*(p0 + p), rb = ra + 1;
        size_t ia = (size_t)(row0 + ra)*Hd + c;
        size_t ib = (size_t)(row0 + rb)*Hd + c;
        float ha = g_h[ia] + o0 / (1.0f + __expf(-g0));
        float hb = g_h[ib] + o1 / (1.0f + __expf(-g1));
        g_h[ia] = ha; g_h[ib] = hb;
        hva[p] = ha; hvb[p] = hb;
    }
    if (do_ln) {
        #pragma unroll
        for (int p = 0; p < 8; p++) {
            int ra = 2*(p0 + p);
            tile[ra][c] = hva[p]; tile[ra+1][c] = hvb[p];
        }
        __syncthreads();
        int warp = tid >> 5, lane = tid & 31;
        #pragma unroll
        for (int rr = 0; rr < 4; rr++) {
            int l = warp*4 + rr;   // 16 warps x 4 = 64 rows
            float v[4]; float sum = 0.f;
            #pragma unroll
            for (int i = 0; i < 4; i++) { v[i] = tile[l][lane + 32*i]; sum += v[i]; }
            #pragma unroll
            for (int o = 16; o; o >>= 1) sum += __shfl_xor_sync(0xffffffffu, sum, o);
            float mu = sum * (1.0f/Hd);
            float var = 0.f;
            #pragma unroll
            for (int i = 0; i < 4; i++) { float t = v[i]-mu; var += t*t; }
            #pragma unroll
            for (int o = 16; o; o >>= 1) var += __shfl_xor_sync(0xffffffffu, var, o);
            float rstd = rsqrtf(var * (1.0f/Hd) + 1e-5f);
            #pragma unroll
            for (int i = 0; i < 4; i++) {
                int cc = lane + 32*i;
                tile[l][cc] = (v[i]-mu)*rstd*nw[cc] + nb[cc];
            }
        }
        __syncthreads();
        for (int idx = tid; idx < 64*Hd; idx += 512) {
            int hh = idx >> 6, l = idx & 63;
            g_hnT[((size_t)(b*Hd + hh))*Lseq + l0 + l] = tile[l][hh];
        }
    }
}

// ---------------- decoder (transposed weights, f32x2 row-pairs) ----------------
__global__ __launch_bounds__(256) void dec_kernel(const float* __restrict__ bias,
                                                  float* __restrict__ out) {
    __shared__ ull zs2[Hd][17];   // (h[2p], h[2p+1]) per channel k; pad 17
    int row0 = blockIdx.x * 32;
    int tid = threadIdx.x;
    for (int idx = tid; idx < Hd*16; idx += 256) {
        int p = idx >> 7, k = idx & 127;
        float v0 = g_h[(size_t)(row0 + 2*p)*Hd + k];
        float v1 = g_h[(size_t)(row0 + 2*p + 1)*Hd + k];
        zs2[k][p] = pk(v0, v1);
    }
    __syncthreads();
    int o = tid & 63, grp = tid >> 6;   // 4 groups x 4 pairs
    ull acc[4];
    {
        float bv = bias[o];
        ull bp = pk(bv, bv);
        #pragma unroll
        for (int p = 0; p < 4; p++) acc[p] = bp;
    }
    #pragma unroll 4
    for (int k = 0; k < Hd; k++) {
        float wv = g_decWT[k*OUTF + o];
        ull wp = pk(wv, wv);
        #pragma unroll
        for (int p = 0; p < 4; p++) acc[p] = ffma2(zs2[k][grp*4 + p], wp, acc[p]);
    }
    #pragma unroll
    for (int p = 0; p < 4; p++) {
        float y0, y1;
        upk(acc[p], y0, y1);
        int pr = grp*4 + p;
        out[(size_t)(row0 + 2*pr)*OUTF + o]     = y0;
        out[(size_t)(row0 + 2*pr + 1)*OUTF + o] = y1;
    }
}

// ---------------- launch ----------------
extern "C" void kernel_launch(void* const* d_in, const int* in_sizes, int n_in,
                              void* d_out, int out_size) {
    const float* x       = (const float*)d_in[0];
    const float* enc_w   = (const float*)d_in[2];
    const float* enc_b   = (const float*)d_in[3];
    const float* dec_w   = (const float*)d_in[4];
    const float* dec_b   = (const float*)d_in[5];
    const float* lam_re  = (const float*)d_in[6];
    const float* lam_im  = (const float*)d_in[7];
    const float* p_re    = (const float*)d_in[8];
    const float* p_im    = (const float*)d_in[9];
    const float* b_re    = (const float*)d_in[10];
    const float* b_im    = (const float*)d_in[11];
    const float* c_re    = (const float*)d_in[12];
    const float* c_im    = (const float*)d_in[13];
    const float* dvec    = (const float*)d_in[14];
    const float* logstep = (const float*)d_in[15];
    const float* norm_w  = (const float*)d_in[16];
    const float* norm_b  = (const float*)d_in[17];
    const float* w1      = (const float*)d_in[18];
    const float* b1      = (const float*)d_in[19];
    const float* w2      = (const float*)d_in[20];
    const float* b2      = (const float*)d_in[21];
    float* out = (float*)d_out;

    int smem_ckfft = 2 * Lseq * (int)sizeof(float2);  // 32 KB (dynamic)
    cudaFuncSetAttribute(ckfft_kernel, cudaFuncAttributeMaxDynamicSharedMemorySize, smem_ckfft);

    prep_kernel<<<(NLAY*Hd*Hd + 255)/256, 256>>>(enc_w, dec_w, w1, w2);
    // all 4 layers' kernel spectra upfront (input-independent)
    ckfft_kernel<<<dim3(Hd, NLAY), 512, smem_ckfft>>>(lam_re, lam_im, p_re, p_im,
                                                      b_re, b_im, c_re, c_im, logstep);
    encoder_kernel<<<ROWS/32, 256>>>(x, enc_b, norm_w, norm_b);  // GEMM + layer-0 LN
    for (int i = 0; i < NLAY; i++) {
        conv_kernel<<<Bsz*Hd/2, 256>>>(dvec + i*Hd, i);
        int last = (i == NLAY-1);
        mlp_kernel<<<ROWS/64, 512>>>(b1 + i*Hd, b2 + i*Hd,
                                     norm_w + (last ? 0 : (i+1)*Hd),
                                     norm_b + (last ? 0 : (i+1)*Hd),
                                     i, last ? 0 : 1);
    }
    dec_kernel<<<ROWS/32, 256>>>(dec_b, out);
}

// round 14
// speedup vs baseline: 1.1031x; 1.1031x over previous
#include <cuda_runtime.h>
#include <math.h>

#define Bsz 8
#define Lseq 2048
#define INF 64
#define OUTF 64
#define Hd 128
#define Nst 64
#define NLAY 4
#define L2 4096
#define ROWS (Bsz*Lseq)

typedef unsigned long long ull;

// ---------------- persistent scratch ----------------
__device__ float  g_h  [ROWS*Hd];          // activations (B,L,H)
__device__ float  g_hnT[Bsz*Hd*Lseq];      // layernormed, transposed (B,H,L)
__device__ float  g_yT [Bsz*Hd*Lseq];      // gelu(conv output), transposed (B,H,L)
__device__ float4 g_KdP[NLAY*(Hd/2)*Lseq]; // spectra f<2048, channel pairs interleaved (K1,K2)
__device__ float2 g_KdN[NLAY*Hd];          // spectrum bin 2048 per channel
__device__ float2 g_tw [L2/2];             // twiddles W_4096^m, m < 2048
__device__ float  g_w1T[NLAY*Hd*Hd];       // transposed weights [k][c]
__device__ float  g_w2T[NLAY*Hd*Hd];
__device__ float  g_encWT[INF*Hd];
__device__ float  g_decWT[Hd*OUTF];

__device__ __forceinline__ float2 cmulf(float2 a, float2 b) {
    return make_float2(a.x*b.x - a.y*b.y, a.x*b.y + a.y*b.x);
}
__device__ __forceinline__ float2 caddf(float2 a, float2 b){ return make_float2(a.x+b.x, a.y+b.y); }
__device__ __forceinline__ float2 csubf(float2 a, float2 b){ return make_float2(a.x-b.x, a.y-b.y); }
// a + sgn*i*d
__device__ __forceinline__ float2 addi(float2 a, float2 d, float sgn) {
    return make_float2(a.x - sgn*d.y, a.y + sgn*d.x);
}
// ---- packed f32x2 helpers ----
__device__ __forceinline__ ull pk(float x, float y) {
    ull r; asm("mov.b64 %0, {%1, %2};" : "=l"(r) : "f"(x), "f"(y)); return r;
}
__device__ __forceinline__ void upk(ull p, float& x, float& y) {
    asm("mov.b64 {%0, %1}, %2;" : "=f"(x), "=f"(y) : "l"(p));
}
__device__ __forceinline__ ull ffma2(ull a, ull b, ull c) {
    ull d; asm("fma.rn.f32x2 %0, %1, %2, %3;" : "=l"(d) : "l"(a), "l"(b), "l"(c)); return d;
}

// ---------------- prep: twiddles + weight transposes (one launch) ----------------
__global__ void prep_kernel(const float* __restrict__ enc_w, const float* __restrict__ dec_w,
                            const float* __restrict__ w1, const float* __restrict__ w2) {
    int tid = blockIdx.x * 256 + threadIdx.x;
    if (tid < L2/2) {
        float s, c;
        sincospif(-(float)tid / 2048.0f, &s, &c);
        g_tw[tid] = make_float2(c, s);
    }
    if (tid < INF*Hd) { int k = tid >> 7, c = tid & 127; g_encWT[tid] = enc_w[c*INF + k]; }
    if (tid < Hd*OUTF) { int k = tid >> 6, o = tid & 63; g_decWT[tid] = dec_w[o*Hd + k]; }
    if (tid < NLAY*Hd*Hd) {
        int lay = tid >> 14, r = tid & 16383, k = r >> 7, c = r & 127;
        g_w1T[tid] = w1[lay*Hd*Hd + c*Hd + k];
        g_w2T[tid] = w2[lay*Hd*Hd + c*Hd + k];
    }
}

// ---------------- radix-8 butterfly (DIT-style: twiddles applied to inputs) ----------------
__device__ __forceinline__ void radix8(const float2 u[8],
                                       float2 w1, float2 w2, float2 w3, float2 w4,
                                       float sgnF, float2 out[8]) {
    const float cc = 0.70710678118654752f;
    float2 w5 = cmulf(w4, w1);
    float2 w6 = cmulf(w3, w3);
    float2 w7 = cmulf(w4, w3);
    float2 t0 = u[0];
    float2 t1 = cmulf(w1, u[1]);
    float2 t2 = cmulf(w2, u[2]);
    float2 t3 = cmulf(w3, u[3]);
    float2 t4 = cmulf(w4, u[4]);
    float2 t5 = cmulf(w5, u[5]);
    float2 t6 = cmulf(w6, u[6]);
    float2 t7 = cmulf(w7, u[7]);
    float2 s04 = caddf(t0, t4), d04 = csubf(t0, t4);
    float2 s26 = caddf(t2, t6), d26 = csubf(t2, t6);
    float2 s15 = caddf(t1, t5), d15 = csubf(t1, t5);
    float2 s37 = caddf(t3, t7), d37 = csubf(t3, t7);
    float2 E0 = caddf(s04, s26), E2 = csubf(s04, s26);
    float2 E1 = addi(d04, d26, sgnF), E3 = addi(d04, d26, -sgnF);
    float2 O0 = caddf(s15, s37), O2 = csubf(s15, s37);
    float2 O1 = addi(d15, d37, sgnF), O3 = addi(d15, d37, -sgnF);
    float2 W81 = make_float2(cc,  sgnF*cc);
    float2 W83 = make_float2(-cc, sgnF*cc);
    float2 p1 = cmulf(O1, W81);
    float2 p2 = make_float2(-sgnF*O2.y, sgnF*O2.x);   // sgnF * i * O2
    float2 p3 = cmulf(O3, W83);
    out[0] = caddf(E0, O0); out[4] = csubf(E0, O0);
    out[1] = caddf(E1, p1); out[5] = csubf(E1, p1);
    out[2] = caddf(E2, p2); out[6] = csubf(E2, p2);
    out[3] = caddf(E3, p3); out[7] = csubf(E3, p3);
}

// ---------------- 2048-pt Stockham FFT: radix-4 then 3x radix-8 (result in `a`) ----------------
__device__ float2* fft2048_m(float2* a, float2* b, bool inverse) {
    float2* src = a; float2* dst = b;
    const float sgnF = inverse ? 1.0f : -1.0f;
    __syncthreads();
    for (int j = threadIdx.x; j < 512; j += blockDim.x) {
        float2 u0 = src[j], u1 = src[j+512], u2 = src[j+1024], u3 = src[j+1536];
        float2 a02 = caddf(u0, u2), s02 = csubf(u0, u2);
        float2 a13 = caddf(u1, u3), s13 = csubf(u1, u3);
        int o = j << 2;
        dst[o  ] = caddf(a02, a13);
        dst[o+1] = addi(s02, s13, sgnF);
        dst[o+2] = csubf(a02, a13);
        dst[o+3] = addi(s02, s13, -sgnF);
    }
    { float2* tmp = src; src = dst; dst = tmp; }
    int L = 4, mult = 128;
    #pragma unroll
    for (int t = 0; t < 3; t++) {
        __syncthreads();
        for (int j = threadIdx.x; j < 256; j += blockDim.x) {
            int k = j & (L - 1);
            int blk = j >> (2 + 3*t);
            float2 u[8];
            #pragma unroll
            for (int i = 0; i < 8; i++) u[i] = src[j + i*256];
            int idx = k * mult;
            float2 w1 = g_tw[idx], w2 = g_tw[2*idx], w3 = g_tw[3*idx], w4 = g_tw[4*idx];
            if (inverse) { w1.y = -w1.y; w2.y = -w2.y; w3.y = -w3.y; w4.y = -w4.y; }
            float2 o8[8];
            radix8(u, w1, w2, w3, w4, sgnF, o8);
            int o = (blk << 3)*L + k;
            #pragma unroll
            for (int i = 0; i < 8; i++) dst[o + i*L] = o8[i];
        }
        { float2* tmp = src; src = dst; dst = tmp; }
        L <<= 3; mult >>= 3;
    }
    __syncthreads();
    return src;
}

// ---------------- one in-place radix-8 stage (4096 pts, 256 threads, 2 bf/thread) ----------------
__device__ __forceinline__ void stage_ip(float2* A, int t, int L, int mult,
                                         float sgnF, bool conj) {
    float2 u[2][8];
    #pragma unroll
    for (int q = 0; q < 2; q++) {
        int j = threadIdx.x + q*256;
        #pragma unroll
        for (int i = 0; i < 8; i++) u[q][i] = A[j + i*512];
    }
    __syncthreads();
    #pragma unroll
    for (int q = 0; q < 2; q++) {
        int j = threadIdx.x + q*256;
        int k = j & (L - 1);
        int blkq = j >> (3*t);
        int idx = k * mult;
        float2 w1 = g_tw[idx], w2 = g_tw[2*idx], w3 = g_tw[3*idx], w4 = g_tw[4*idx];
        if (conj) { w1.y = -w1.y; w2.y = -w2.y; w3.y = -w3.y; w4.y = -w4.y; }
        float2 o8[8];
        radix8(u[q], w1, w2, w3, w4, sgnF, o8);
        int o = (blkq << (3*t + 3)) + k;
        #pragma unroll
        for (int i = 0; i < 8; i++) A[o + i*L] = o8[i];
    }
    __syncthreads();
}

// ---------------- FFT causal conv, in-place single-buffer (32 KB), real-kernel symmetry ----------------
__global__ __launch_bounds__(256, 4) void conv_kernel(const float* __restrict__ dvec, int lay) {
    __shared__ float2 A[L2];
    int blk = blockIdx.x;
    int b = blk >> 6, hp = blk & 63;
    int h0 = 2*hp;
    int tid = threadIdx.x;
    const float* u1 = g_hnT + ((size_t)b*Hd + h0)*Lseq;
    const float* u2 = u1 + Lseq;
    const float2 ONE = make_float2(1.f, 0.f);

    // forward stage 0 (L=1, twiddles=1): global -> butterflies -> A; upper half is zero
    #pragma unroll
    for (int q = 0; q < 2; q++) {
        int j = tid + q*256;
        float2 u[8], o8[8];
        #pragma unroll
        for (int i = 0; i < 4; i++) u[i] = make_float2(u1[j + i*512], u2[j + i*512]);
        #pragma unroll
        for (int i = 4; i < 8; i++) u[i] = make_float2(0.f, 0.f);
        radix8(u, ONE, ONE, ONE, ONE, -1.0f, o8);
        #pragma unroll
        for (int i = 0; i < 8; i++) A[(j << 3) + i] = o8[i];
    }
    __syncthreads();
    // forward stages 1..3
    stage_ip(A, 1, 8,   64, -1.0f, false);
    stage_ip(A, 2, 64,  8,  -1.0f, false);
    stage_ip(A, 3, 512, 1,  -1.0f, false);

    // pointwise using K-real symmetry: compute Y at f<2048 once, emit f and 4096-f.
    const float4* KP = g_KdP + ((size_t)lay*(Hd/2) + hp)*Lseq;
    #pragma unroll
    for (int s = 0; s < 8; s++) {
        int f  = tid + s*256;              // 0..2047
        int fr = (L2 - f) & (L2-1);
        float2 zf = A[f], zr = A[fr];
        float4 K = KP[f];
        float2 K1 = make_float2(K.x, K.y), K2 = make_float2(K.z, K.w);
        float2 U1 = make_float2(0.5f*(zf.x + zr.x),  0.5f*(zf.y - zr.y));
        float2 U2 = make_float2(0.5f*(zf.y + zr.y), -0.5f*(zf.x - zr.x));
        float2 Y1 = cmulf(U1, K1);
        float2 Y2 = cmulf(U2, K2);
        A[f] = make_float2(Y1.x - Y2.y, Y1.y + Y2.x);
        if (f != 0)
            A[fr] = make_float2(Y1.x + Y2.y, Y2.x - Y1.y);   // conj(Y1) + i*conj(Y2)
        if (f == 0) {   // self-paired Nyquist bin 2048
            float2 z = A[2048];
            float2 K1n = g_KdN[lay*Hd + h0];
            float2 K2n = g_KdN[lay*Hd + h0 + 1];
            float2 Y1n = make_float2(z.x*K1n.x, z.x*K1n.y);
            float2 Y2n = make_float2(z.y*K2n.x, z.y*K2n.y);
            A[2048] = make_float2(Y1n.x - Y2n.y, Y1n.y + Y2n.x);
        }
    }
    __syncthreads();

    // inverse stage 0 (L=1, twiddles=1)
    {
        float2 u[2][8];
        #pragma unroll
        for (int q = 0; q < 2; q++) {
            int j = tid + q*256;
            #pragma unroll
            for (int i = 0; i < 8; i++) u[q][i] = A[j + i*512];
        }
        __syncthreads();
        #pragma unroll
        for (int q = 0; q < 2; q++) {
            int j = tid + q*256;
            float2 o8[8];
            radix8(u[q], ONE, ONE, ONE, ONE, 1.0f, o8);
            #pragma unroll
            for (int i = 0; i < 8; i++) A[(j << 3) + i] = o8[i];
        }
        __syncthreads();
    }
    stage_ip(A, 1, 8,  64, 1.0f, true);
    stage_ip(A, 2, 64, 8,  1.0f, true);
    // inverse stage 3 fused with epilogue: keep only l < 2048 (i < 4), write global
    {
        float d1 = dvec[h0], d2 = dvec[h0+1];
        float* y1 = g_yT + ((size_t)b*Hd + h0)*Lseq;
        float* y2 = y1 + Lseq;
        float2 u[2][8];
        #pragma unroll
        for (int q = 0; q < 2; q++) {
            int j = tid + q*256;
            #pragma unroll
            for (int i = 0; i < 8; i++) u[q][i] = A[j + i*512];
        }
        // no smem writes follow -> no barrier needed
        #pragma unroll
        for (int q = 0; q < 2; q++) {
            int j = tid + q*256;          // k = j (L=512), blk = 0
            int idx = j;                   // mult = 1
            float2 w1 = g_tw[idx], w2 = g_tw[2*idx], w3 = g_tw[3*idx], w4 = g_tw[4*idx];
            w1.y = -w1.y; w2.y = -w2.y; w3.y = -w3.y; w4.y = -w4.y;
            float2 o8[8];
            radix8(u[q], w1, w2, w3, w4, 1.0f, o8);
            #pragma unroll
            for (int i = 0; i < 4; i++) {
                int l = j + i*512;
                float v1 = o8[i].x*(1.0f/L2) + u1[l]*d1;
                float v2 = o8[i].y*(1.0f/L2) + u2[l]*d2;
                float t1 = 0.7978845608028654f * (v1 + 0.044715f * v1*v1*v1);
                float t2 = 0.7978845608028654f * (v2 + 0.044715f * v2*v2*v2);
                y1[l] = 0.5f * v1 * (1.0f + tanhf(t1));
                y2[l] = 0.5f * v2 * (1.0f + tanhf(t2));
            }
        }
    }
}

// ---------------- encoder GEMM (f32x2 row-pairs) + fused layer-0 LN -> g_h, g_hnT ----------------
__global__ __launch_bounds__(256) void encoder_kernel(const float* __restrict__ x,
                                                      const float* __restrict__ eb,
                                                      const float* __restrict__ nw,
                                                      const float* __restrict__ nb) {
    __shared__ float xs[32][INF];     // staged input rows
    __shared__ ull   zs2[INF][17];    // packed row-pairs (pad 17 to break bank conflicts)
    __shared__ float tile[32][129];   // h rows for LN
    int row0 = blockIdx.x * 32;
    int b = row0 >> 11, l0 = row0 & 2047;
    int tid = threadIdx.x;
    for (int idx = tid; idx < 32*INF; idx += 256)
        xs[idx >> 6][idx & 63] = x[(size_t)(row0 + (idx >> 6))*INF + (idx & 63)];
    __syncthreads();
    for (int idx = tid; idx < INF*16; idx += 256) {
        int p = idx >> 6, k = idx & 63;
        zs2[k][p] = pk(xs[2*p][k], xs[2*p+1][k]);
    }
    __syncthreads();
    int c = tid & 127, half = tid >> 7;
    int p0 = half * 8;
    ull acc[8];
    {
        float bv = eb[c];
        ull bp = pk(bv, bv);
        #pragma unroll
        for (int p = 0; p < 8; p++) acc[p] = bp;
    }
    #pragma unroll 4
    for (int k = 0; k < INF; k++) {
        float wv = g_encWT[k*Hd + c];
        ull wp = pk(wv, wv);
        #pragma unroll
        for (int p = 0; p < 8; p++) acc[p] = ffma2(zs2[k][p0 + p], wp, acc[p]);
    }
    #pragma unroll
    for (int p = 0; p < 8; p++) {
        float h0v, h1v;
        upk(acc[p], h0v, h1v);
        int ra = 2*(p0 + p), rb = ra + 1;
        g_h[(size_t)(row0 + ra)*Hd + c] = h0v;
        g_h[(size_t)(row0 + rb)*Hd + c] = h1v;
        tile[ra][c] = h0v; tile[rb][c] = h1v;
    }
    __syncthreads();
    int warp = tid >> 5, lane = tid & 31;
    #pragma unroll
    for (int rr = 0; rr < 4; rr++) {
        int l = warp*4 + rr;
        float v[4]; float sum = 0.f;
        #pragma unroll
        for (int i = 0; i < 4; i++) { v[i] = tile[l][lane + 32*i]; sum += v[i]; }
        #pragma unroll
        for (int o = 16; o; o >>= 1) sum += __shfl_xor_sync(0xffffffffu, sum, o);
        float mu = sum * (1.0f/Hd);
        float var = 0.f;
        #pragma unroll
        for (int i = 0; i < 4; i++) { float t = v[i]-mu; var += t*t; }
        #pragma unroll
        for (int o = 16; o; o >>= 1) var += __shfl_xor_sync(0xffffffffu, var, o);
        float rstd = rsqrtf(var * (1.0f/Hd) + 1e-5f);
        #pragma unroll
        for (int i = 0; i < 4; i++) {
            int cc = lane + 32*i;
            tile[l][cc] = (v[i]-mu)*rstd*nw[cc] + nb[cc];
        }
    }
    __syncthreads();
    for (int idx = tid; idx < 32*Hd; idx += 256) {
        int hh = idx >> 5, l = idx & 31;
        g_hnT[((size_t)(b*Hd + hh))*Lseq + l0 + l] = tile[l][hh];
    }
}

// ---------------- FUSED cauchy + kernel-spectrum, n-outer register-blocked cauchy ----------------
__global__ __launch_bounds__(512) void ckfft_kernel(
        const float* __restrict__ lre, const float* __restrict__ lim,
        const float* __restrict__ pre, const float* __restrict__ pim,
        const float* __restrict__ bre, const float* __restrict__ bim,
        const float* __restrict__ cre, const float* __restrict__ cim,
        const float* __restrict__ lstep) {
    extern __shared__ float2 sm[];
    float2* A  = sm;           // 2048
    float2* Bb = sm + Lseq;    // 2048
    __shared__ float2 slam[Nst];
    __shared__ ull sp[4][Nst][2];
    int h = blockIdx.x, lay = blockIdx.y;
    int hh = lay*Hd + h;
    int tid = threadIdx.x;
    if (tid < Nst) {
        int idx = hh*Nst + tid;
        slam[tid] = make_float2(lre[idx], lim[idx]);
        float2 P  = make_float2(pre[idx], pim[idx]);
        float2 Bv = make_float2(bre[idx], bim[idx]);
        float2 Cc = make_float2(cre[idx], -cim[idx]);
        float2 Pc = make_float2(P.x, -P.y);
        float2 vm[4];
        vm[0] = cmulf(Cc, Bv); vm[1] = cmulf(Cc, P);
        vm[2] = cmulf(Pc, Bv); vm[3] = cmulf(Pc, P);
        #pragma unroll
        for (int m = 0; m < 4; m++) {
            sp[m][tid][0] = pk(vm[m].x, vm[m].y);
            sp[m][tid][1] = pk(vm[m].y, -vm[m].x);
        }
    }
    __syncthreads();
    float ts = 2.0f / __expf(lstep[hh]);
    // per-thread l values: l = tid + q*512, q=0..3
    float gxv[4], gyv[4], c2xv[4], c2yv[4];
    #pragma unroll
    for (int q = 0; q < 4; q++) {
        int l = tid + q*512;
        // XLA-style omega (f32 angle + sincosf; l=L/2 must NOT be exactly -1)
        float ang = -6.2831853071795864f * ((float)l / (float)Lseq);
        float s, c;
        sincosf(ang, &s, &c);
        float dpx = 1.0f + c, dpy = s;
        float dmx = 1.0f - c, dmy = -s;
        float id2 = __fdividef(1.0f, dpx*dpx + dpy*dpy);
        gxv[q] = ts * (dmx*dpx + dmy*dpy) * id2;
        gyv[q] = ts * (dmy*dpx - dmx*dpy) * id2;
        c2xv[q] = 2.0f*dpx*id2;
        c2yv[q] = -2.0f*dpy*id2;
    }
    ull acc[4][4];   // [q][m], packed (kx, ky)
    #pragma unroll
    for (int q = 0; q < 4; q++)
        #pragma unroll
        for (int m = 0; m < 4; m++) acc[q][m] = 0ull;
    #pragma unroll 2
    for (int n = 0; n < Nst; n++) {
        float2 lam = slam[n];
        ull s0[4], s1[4];
        #pragma unroll
        for (int m = 0; m < 4; m++) { s0[m] = sp[m][n][0]; s1[m] = sp[m][n][1]; }
        #pragma unroll
        for (int q = 0; q < 4; q++) {
            float dx = gxv[q] - lam.x;
            float dy = gyv[q] - lam.y;
            float inv = __fdividef(1.0f, dx*dx + dy*dy);
            float rx = dx*inv, ryp = dy*inv;
            ull rxx = pk(rx, rx), ryy = pk(ryp, ryp);
            #pragma unroll
            for (int m = 0; m < 4; m++)
                acc[q][m] = ffma2(s0[m], rxx, ffma2(s1[m], ryy, acc[q][m]));
        }
    }
    #pragma unroll
    for (int q = 0; q < 4; q++) {
        int l = tid + q*512;
        float k00x,k00y,k01x,k01y,k10x,k10y,k11x,k11y;
        upk(acc[q][0], k00x, k00y); upk(acc[q][1], k01x, k01y);
        upk(acc[q][2], k10x, k10y); upk(acc[q][3], k11x, k11y);
        float opx = 1.0f + k11x, opy = k11y;
        float oinv = __fdividef(1.0f, opx*opx + opy*opy);
        float wx = k01x*k10x - k01y*k10y;
        float wy = k01x*k10y + k01y*k10x;
        float cx = (wx*opx + wy*opy) * oinv;
        float cy = (wy*opx - wx*opy) * oinv;
        float rx2 = k00x - cx, ry2 = k00y - cy;
        A[l] = make_float2(c2xv[q]*rx2 - c2yv[q]*ry2, c2xv[q]*ry2 + c2yv[q]*rx2);
    }
    __syncthreads();
    // Kd storage: pair-interleaved float4 (slot h&1), f<2048 only; bin 2048 separate.
    float2* KP2 = (float2*)(g_KdP + ((size_t)lay*(Hd/2) + (h>>1))*Lseq);  // index 2*f + slot
    int slot = h & 1;
    // even bins from at (A) BEFORE the in-place IFFT destroys it
    for (int m = tid; m < Lseq; m += 512) {
        if (m < 1024) {
            float2 am = A[m];
            float2 ar = A[(Lseq - m) & (Lseq-1)];
            KP2[4*m + slot] = make_float2(0.5f*(am.x + ar.x), 0.5f*(am.y - ar.y));  // f=2m
        } else if (m == 1024) {
            g_KdN[hh] = make_float2(A[1024].x, 0.f);   // bin 2048
        }
    }
    float2* r = fft2048_m(A, Bb, true);
    for (int m = tid; m < Lseq; m += 512) {
        float xr = r[m].x * (1.0f/Lseq);
        float2 w = g_tw[m];
        Bb[m] = make_float2(xr * w.x, xr * w.y);
    }
    float2* r2 = fft2048_m(Bb, A, false);
    for (int m = tid; m < 1024; m += 512)
        KP2[4*m + 2 + slot] = r2[m];                   // f=2m+1
}

// ---------------- gated MLP + residual + fused next-layer LN (64 rows, 512 threads) ----------------
__global__ __launch_bounds__(512) void mlp_kernel(const float* __restrict__ b1,
                                                  const float* __restrict__ b2,
                                                  const float* __restrict__ nw,
                                                  const float* __restrict__ nb,
                                                  int lay, int do_ln) {
    const float* __restrict__ w1T = g_w1T + lay*Hd*Hd;
    const float* __restrict__ w2T = g_w2T + lay*Hd*Hd;
    // union: zs2 (32 KB, GEMM phase) then tile (33 KB, LN phase)
    __shared__ __align__(16) unsigned char smbuf[64*129*4];
    ull   (*zs2)[32]  = reinterpret_cast<ull(*)[32]>(smbuf);
    float (*tile)[129] = reinterpret_cast<float(*)[129]>(smbuf);
    int row0 = blockIdx.x * 64;
    int b = row0 >> 11, l0 = row0 & 2047;
    int tid = threadIdx.x;
    int c = tid & 127, grp = tid >> 7;   // 4 groups
    for (int idx = tid; idx < Hd*32; idx += 512) {
        int k = idx >> 5, p = idx & 31;
        float2 v = *(const float2*)&g_yT[((size_t)(b*Hd + k))*Lseq + l0 + 2*p];
        zs2[k][p] = pk(v.x, v.y);
    }
    __syncthreads();
    int p0 = grp * 8;
    ull acc1[8], acc2[8];
    {
        float b1v = b1[c], b2v = b2[c];
        ull p1 = pk(b1v, b1v), p2 = pk(b2v, b2v);
        #pragma unroll
        for (int p = 0; p < 8; p++) { acc1[p] = p1; acc2[p] = p2; }
    }
    #pragma unroll 2
    for (int k = 0; k < Hd; k++) {
        float w1v = w1T[k*Hd + c];
        float w2v = w2T[k*Hd + c];
        ull w1p = pk(w1v, w1v), w2p = pk(w2v, w2v);
        #pragma unroll
        for (int p = 0; p < 8; p++) {
            ull zp = zs2[k][p0 + p];
            acc1[p] = ffma2(zp, w1p, acc1[p]);
            acc2[p] = ffma2(zp, w2p, acc2[p]);
        }
    }
    __syncthreads();   // zs2 dead; tile may now alias it
    float hva[8], hvb[8];
    #pragma unroll
    for (int p = 0; p < 8; p++) {
        float o0, o1, g0, g1;
        upk(acc1[p], o0, o1);
        upk(acc2[p], g0, g1);
        int ra = 2*(p0 + p), rb = ra + 1;
        size_t ia = (size_t)(row0 + ra)*Hd + c;
        size_t ib = (size_t)(row0 + rb)*Hd + c;
        float ha = g_h[ia] + o0 / (1.0f + __expf(-g0));
        float hb = g_h[ib] + o1 / (1.0f + __expf(-g1));
        g_h[ia] = ha; g_h[ib] = hb;
        hva[p] = ha; hvb[p] = hb;
    }
    if (do_ln) {
        #pragma unroll
        for (int p = 0; p < 8; p++) {
            int ra = 2*(p0 + p);
            tile[ra][c] = hva[p]; tile[ra+1][c] = hvb[p];
        }
        __syncthreads();
        int warp = tid >> 5, lane = tid & 31;
        #pragma unroll
        for (int rr = 0; rr < 4; rr++) {
            int l = warp*4 + rr;   // 16 warps x 4 = 64 rows
            float v[4]; float sum = 0.f;
            #pragma unroll
            for (int i = 0; i < 4; i++) { v[i] = tile[l][lane + 32*i]; sum += v[i]; }
            #pragma unroll
            for (int o = 16; o; o >>= 1) sum += __shfl_xor_sync(0xffffffffu, sum, o);
            float mu = sum * (1.0f/Hd);
            float var = 0.f;
            #pragma unroll
            for (int i = 0; i < 4; i++) { float t = v[i]-mu; var += t*t; }
            #pragma unroll
            for (int o = 16; o; o >>= 1) var += __shfl_xor_sync(0xffffffffu, var, o);
            float rstd = rsqrtf(var * (1.0f/Hd) + 1e-5f);
            #pragma unroll
            for (int i = 0; i < 4; i++) {
                int cc = lane + 32*i;
                tile[l][cc] = (v[i]-mu)*rstd*nw[cc] + nb[cc];
            }
        }
        __syncthreads();
        for (int idx = tid; idx < 64*Hd; idx += 512) {
            int hh = idx >> 6, l = idx & 63;
            g_hnT[((size_t)(b*Hd + hh))*Lseq + l0 + l] = tile[l][hh];
        }
    }
}

// ---------------- decoder (transposed weights, f32x2 row-pairs) ----------------
__global__ __launch_bounds__(256) void dec_kernel(const float* __restrict__ bias,
                                                  float* __restrict__ out) {
    __shared__ ull zs2[Hd][17];   // (h[2p], h[2p+1]) per channel k; pad 17
    int row0 = blockIdx.x * 32;
    int tid = threadIdx.x;
    for (int idx = tid; idx < Hd*16; idx += 256) {
        int p = idx >> 7, k = idx & 127;
        float v0 = g_h[(size_t)(row0 + 2*p)*Hd + k];
        float v1 = g_h[(size_t)(row0 + 2*p + 1)*Hd + k];
        zs2[k][p] = pk(v0, v1);
    }
    __syncthreads();
    int o = tid & 63, grp = tid >> 6;   // 4 groups x 4 pairs
    ull acc[4];
    {
        float bv = bias[o];
        ull bp = pk(bv, bv);
        #pragma unroll
        for (int p = 0; p < 4; p++) acc[p] = bp;
    }
    #pragma unroll 4
    for (int k = 0; k < Hd; k++) {
        float wv = g_decWT[k*OUTF + o];
        ull wp = pk(wv, wv);
        #pragma unroll
        for (int p = 0; p < 4; p++) acc[p] = ffma2(zs2[k][grp*4 + p], wp, acc[p]);
    }
    #pragma unroll
    for (int p = 0; p < 4; p++) {
        float y0, y1;
        upk(acc[p], y0, y1);
        int pr = grp*4 + p;
        out[(size_t)(row0 + 2*pr)*OUTF + o]     = y0;
        out[(size_t)(row0 + 2*pr + 1)*OUTF + o] = y1;
    }
}

// ---------------- launch ----------------
extern "C" void kernel_launch(void* const* d_in, const int* in_sizes, int n_in,
                              void* d_out, int out_size) {
    const float* x       = (const float*)d_in[0];
    const float* enc_w   = (const float*)d_in[2];
    const float* enc_b   = (const float*)d_in[3];
    const float* dec_w   = (const float*)d_in[4];
    const float* dec_b   = (const float*)d_in[5];
    const float* lam_re  = (const float*)d_in[6];
    const float* lam_im  = (const float*)d_in[7];
    const float* p_re    = (const float*)d_in[8];
    const float* p_im    = (const float*)d_in[9];
    const float* b_re    = (const float*)d_in[10];
    const float* b_im    = (const float*)d_in[11];
    const float* c_re    = (const float*)d_in[12];
    const float* c_im    = (const float*)d_in[13];
    const float* dvec    = (const float*)d_in[14];
    const float* logstep = (const float*)d_in[15];
    const float* norm_w  = (const float*)d_in[16];
    const float* norm_b  = (const float*)d_in[17];
    const float* w1      = (const float*)d_in[18];
    const float* b1      = (const float*)d_in[19];
    const float* w2      = (const float*)d_in[20];
    const float* b2      = (const float*)d_in[21];
    float* out = (float*)d_out;

    int smem_ckfft = 2 * Lseq * (int)sizeof(float2);  // 32 KB (dynamic)
    cudaFuncSetAttribute(ckfft_kernel, cudaFuncAttributeMaxDynamicSharedMemorySize, smem_ckfft);

    prep_kernel<<<(NLAY*Hd*Hd + 255)/256, 256>>>(enc_w, dec_w, w1, w2);
    // all 4 layers' kernel spectra upfront (input-independent)
    ckfft_kernel<<<dim3(Hd, NLAY), 512, smem_ckfft>>>(lam_re, lam_im, p_re, p_im,
                                                      b_re, b_im, c_re, c_im, logstep);
    encoder_kernel<<<ROWS/32, 256>>>(x, enc_b, norm_w, norm_b);  // GEMM + layer-0 LN
    for (int i = 0; i < NLAY; i++) {
        conv_kernel<<<Bsz*Hd/2, 256>>>(dvec + i*Hd, i);
        int last = (i == NLAY-1);
        mlp_kernel<<<ROWS/64, 512>>>(b1 + i*Hd, b2 + i*Hd,
                                     norm_w + (last ? 0 : (i+1)*Hd),
                                     norm_b + (last ? 0 : (i+1)*Hd),
                                     i, last ? 0 : 1);
    }
    dec_kernel<<<ROWS/32, 256>>>(dec_b, out);
}

// round 15
// speedup vs baseline: 1.1202x; 1.0154x over previous
#include <cuda_runtime.h>
#include <math.h>

#define Bsz 8
#define Lseq 2048
#define INF 64
#define OUTF 64
#define Hd 128
#define Nst 64
#define NLAY 4
#define L2 4096
#define ROWS (Bsz*Lseq)

typedef unsigned long long ull;

// ---------------- persistent scratch ----------------
__device__ float  g_h  [ROWS*Hd];          // activations (B,L,H)
__device__ float  g_hnT[Bsz*Hd*Lseq];      // layernormed, transposed (B,H,L)
__device__ float  g_yT [Bsz*Hd*Lseq];      // gelu(conv output), transposed (B,H,L)
__device__ float4 g_KdP[NLAY*(Hd/2)*Lseq]; // spectra f<2048, channel pairs interleaved (K1,K2)
__device__ float2 g_KdN[NLAY*Hd];          // spectrum bin 2048 per channel
__device__ float2 g_tw [L2/2];             // twiddles W_4096^m, m < 2048
__device__ float  g_w1T[NLAY*Hd*Hd];       // transposed weights [k][c]
__device__ float  g_w2T[NLAY*Hd*Hd];
__device__ float  g_encWT[INF*Hd];
__device__ float  g_decWT[Hd*OUTF];

__device__ __forceinline__ float2 cmulf(float2 a, float2 b) {
    return make_float2(a.x*b.x - a.y*b.y, a.x*b.y + a.y*b.x);
}
__device__ __forceinline__ float2 caddf(float2 a, float2 b){ return make_float2(a.x+b.x, a.y+b.y); }
__device__ __forceinline__ float2 csubf(float2 a, float2 b){ return make_float2(a.x-b.x, a.y-b.y); }
__device__ __forceinline__ float2 addi(float2 a, float2 d, float sgn) {
    return make_float2(a.x - sgn*d.y, a.y + sgn*d.x);
}
__device__ __forceinline__ ull pk(float x, float y) {
    ull r; asm("mov.b64 %0, {%1, %2};" : "=l"(r) : "f"(x), "f"(y)); return r;
}
__device__ __forceinline__ void upk(ull p, float& x, float& y) {
    asm("mov.b64 {%0, %1}, %2;" : "=f"(x), "=f"(y) : "l"(p));
}
__device__ __forceinline__ ull ffma2(ull a, ull b, ull c) {
    ull d; asm("fma.rn.f32x2 %0, %1, %2, %3;" : "=l"(d) : "l"(a), "l"(b), "l"(c)); return d;
}

// ---------------- prep: twiddles + weight transposes ----------------
__global__ void prep_kernel(const float* __restrict__ enc_w, const float* __restrict__ dec_w,
                            const float* __restrict__ w1, const float* __restrict__ w2) {
    int tid = blockIdx.x * 256 + threadIdx.x;
    if (tid < L2/2) {
        float s, c;
        sincospif(-(float)tid / 2048.0f, &s, &c);
        g_tw[tid] = make_float2(c, s);
    }
    if (tid < INF*Hd) { int k = tid >> 7, c = tid & 127; g_encWT[tid] = enc_w[c*INF + k]; }
    if (tid < Hd*OUTF) { int k = tid >> 6, o = tid & 63; g_decWT[tid] = dec_w[o*Hd + k]; }
    if (tid < NLAY*Hd*Hd) {
        int lay = tid >> 14, r = tid & 16383, k = r >> 7, c = r & 127;
        g_w1T[tid] = w1[lay*Hd*Hd + c*Hd + k];
        g_w2T[tid] = w2[lay*Hd*Hd + c*Hd + k];
    }
}

// ---------------- radix-8 butterfly ----------------
__device__ __forceinline__ void radix8(const float2 u[8],
                                       float2 w1, float2 w2, float2 w3, float2 w4,
                                       float sgnF, float2 out[8]) {
    const float cc = 0.70710678118654752f;
    float2 w5 = cmulf(w4, w1);
    float2 w6 = cmulf(w3, w3);
    float2 w7 = cmulf(w4, w3);
    float2 t0 = u[0];
    float2 t1 = cmulf(w1, u[1]);
    float2 t2 = cmulf(w2, u[2]);
    float2 t3 = cmulf(w3, u[3]);
    float2 t4 = cmulf(w4, u[4]);
    float2 t5 = cmulf(w5, u[5]);
    float2 t6 = cmulf(w6, u[6]);
    float2 t7 = cmulf(w7, u[7]);
    float2 s04 = caddf(t0, t4), d04 = csubf(t0, t4);
    float2 s26 = caddf(t2, t6), d26 = csubf(t2, t6);
    float2 s15 = caddf(t1, t5), d15 = csubf(t1, t5);
    float2 s37 = caddf(t3, t7), d37 = csubf(t3, t7);
    float2 E0 = caddf(s04, s26), E2 = csubf(s04, s26);
    float2 E1 = addi(d04, d26, sgnF), E3 = addi(d04, d26, -sgnF);
    float2 O0 = caddf(s15, s37), O2 = csubf(s15, s37);
    float2 O1 = addi(d15, d37, sgnF), O3 = addi(d15, d37, -sgnF);
    float2 W81 = make_float2(cc,  sgnF*cc);
    float2 W83 = make_float2(-cc, sgnF*cc);
    float2 p1 = cmulf(O1, W81);
    float2 p2 = make_float2(-sgnF*O2.y, sgnF*O2.x);
    float2 p3 = cmulf(O3, W83);
    out[0] = caddf(E0, O0); out[4] = csubf(E0, O0);
    out[1] = caddf(E1, p1); out[5] = csubf(E1, p1);
    out[2] = caddf(E2, p2); out[6] = csubf(E2, p2);
    out[3] = caddf(E3, p3); out[7] = csubf(E3, p3);
}

// ---------------- 2048-pt Stockham FFT (double-buffered; ckfft only) ----------------
__device__ float2* fft2048_m(float2* a, float2* b, bool inverse) {
    float2* src = a; float2* dst = b;
    const float sgnF = inverse ? 1.0f : -1.0f;
    __syncthreads();
    for (int j = threadIdx.x; j < 512; j += blockDim.x) {
        float2 u0 = src[j], u1 = src[j+512], u2 = src[j+1024], u3 = src[j+1536];
        float2 a02 = caddf(u0, u2), s02 = csubf(u0, u2);
        float2 a13 = caddf(u1, u3), s13 = csubf(u1, u3);
        int o = j << 2;
        dst[o  ] = caddf(a02, a13);
        dst[o+1] = addi(s02, s13, sgnF);
        dst[o+2] = csubf(a02, a13);
        dst[o+3] = addi(s02, s13, -sgnF);
    }
    { float2* tmp = src; src = dst; dst = tmp; }
    int L = 4, mult = 128;
    #pragma unroll
    for (int t = 0; t < 3; t++) {
        __syncthreads();
        for (int j = threadIdx.x; j < 256; j += blockDim.x) {
            int k = j & (L - 1);
            int blk = j >> (2 + 3*t);
            float2 u[8];
            #pragma unroll
            for (int i = 0; i < 8; i++) u[i] = src[j + i*256];
            int idx = k * mult;
            float2 w1 = g_tw[idx], w2 = g_tw[2*idx], w3 = g_tw[3*idx], w4 = g_tw[4*idx];
            if (inverse) { w1.y = -w1.y; w2.y = -w2.y; w3.y = -w3.y; w4.y = -w4.y; }
            float2 o8[8];
            radix8(u, w1, w2, w3, w4, sgnF, o8);
            int o = (blk << 3)*L + k;
            #pragma unroll
            for (int i = 0; i < 8; i++) dst[o + i*L] = o8[i];
        }
        { float2* tmp = src; src = dst; dst = tmp; }
        L <<= 3; mult >>= 3;
    }
    __syncthreads();
    return src;
}

// ---------------- one in-place radix-8 stage (4096 pts, 256 threads) ----------------
__device__ __forceinline__ void stage_ip(float2* A, int t, int L, int mult,
                                         float sgnF, bool conj) {
    float2 u[2][8];
    #pragma unroll
    for (int q = 0; q < 2; q++) {
        int j = threadIdx.x + q*256;
        #pragma unroll
        for (int i = 0; i < 8; i++) u[q][i] = A[j + i*512];
    }
    __syncthreads();
    #pragma unroll
    for (int q = 0; q < 2; q++) {
        int j = threadIdx.x + q*256;
        int k = j & (L - 1);
        int blkq = j >> (3*t);
        int idx = k * mult;
        float2 w1 = g_tw[idx], w2 = g_tw[2*idx], w3 = g_tw[3*idx], w4 = g_tw[4*idx];
        if (conj) { w1.y = -w1.y; w2.y = -w2.y; w3.y = -w3.y; w4.y = -w4.y; }
        float2 o8[8];
        radix8(u[q], w1, w2, w3, w4, sgnF, o8);
        int o = (blkq << (3*t + 3)) + k;
        #pragma unroll
        for (int i = 0; i < 8; i++) A[o + i*L] = o8[i];
    }
    __syncthreads();
}

// ---------------- FFT causal conv (R14 winner, unchanged) ----------------
__global__ __launch_bounds__(256, 4) void conv_kernel(const float* __restrict__ dvec, int lay) {
    __shared__ float2 A[L2];
    int blk = blockIdx.x;
    int b = blk >> 6, hp = blk & 63;
    int h0 = 2*hp;
    int tid = threadIdx.x;
    const float* u1 = g_hnT + ((size_t)b*Hd + h0)*Lseq;
    const float* u2 = u1 + Lseq;
    const float2 ONE = make_float2(1.f, 0.f);

    #pragma unroll
    for (int q = 0; q < 2; q++) {
        int j = tid + q*256;
        float2 u[8], o8[8];
        #pragma unroll
        for (int i = 0; i < 4; i++) u[i] = make_float2(u1[j + i*512], u2[j + i*512]);
        #pragma unroll
        for (int i = 4; i < 8; i++) u[i] = make_float2(0.f, 0.f);
        radix8(u, ONE, ONE, ONE, ONE, -1.0f, o8);
        #pragma unroll
        for (int i = 0; i < 8; i++) A[(j << 3) + i] = o8[i];
    }
    __syncthreads();
    stage_ip(A, 1, 8,   64, -1.0f, false);
    stage_ip(A, 2, 64,  8,  -1.0f, false);
    stage_ip(A, 3, 512, 1,  -1.0f, false);

    const float4* KP = g_KdP + ((size_t)lay*(Hd/2) + hp)*Lseq;
    #pragma unroll
    for (int s = 0; s < 8; s++) {
        int f  = tid + s*256;
        int fr = (L2 - f) & (L2-1);
        float2 zf = A[f], zr = A[fr];
        float4 K = KP[f];
        float2 K1 = make_float2(K.x, K.y), K2 = make_float2(K.z, K.w);
        float2 U1 = make_float2(0.5f*(zf.x + zr.x),  0.5f*(zf.y - zr.y));
        float2 U2 = make_float2(0.5f*(zf.y + zr.y), -0.5f*(zf.x - zr.x));
        float2 Y1 = cmulf(U1, K1);
        float2 Y2 = cmulf(U2, K2);
        A[f] = make_float2(Y1.x - Y2.y, Y1.y + Y2.x);
        if (f != 0)
            A[fr] = make_float2(Y1.x + Y2.y, Y2.x - Y1.y);
        if (f == 0) {
            float2 z = A[2048];
            float2 K1n = g_KdN[lay*Hd + h0];
            float2 K2n = g_KdN[lay*Hd + h0 + 1];
            float2 Y1n = make_float2(z.x*K1n.x, z.x*K1n.y);
            float2 Y2n = make_float2(z.y*K2n.x, z.y*K2n.y);
            A[2048] = make_float2(Y1n.x - Y2n.y, Y1n.y + Y2n.x);
        }
    }
    __syncthreads();

    {
        float2 u[2][8];
        #pragma unroll
        for (int q = 0; q < 2; q++) {
            int j = tid + q*256;
            #pragma unroll
            for (int i = 0; i < 8; i++) u[q][i] = A[j + i*512];
        }
        __syncthreads();
        #pragma unroll
        for (int q = 0; q < 2; q++) {
            int j = tid + q*256;
            float2 o8[8];
            radix8(u[q], ONE, ONE, ONE, ONE, 1.0f, o8);
            #pragma unroll
            for (int i = 0; i < 8; i++) A[(j << 3) + i] = o8[i];
        }
        __syncthreads();
    }
    stage_ip(A, 1, 8,  64, 1.0f, true);
    stage_ip(A, 2, 64, 8,  1.0f, true);
    {
        float d1 = dvec[h0], d2 = dvec[h0+1];
        float* y1 = g_yT + ((size_t)b*Hd + h0)*Lseq;
        float* y2 = y1 + Lseq;
        float2 u[2][8];
        #pragma unroll
        for (int q = 0; q < 2; q++) {
            int j = tid + q*256;
            #pragma unroll
            for (int i = 0; i < 8; i++) u[q][i] = A[j + i*512];
        }
        #pragma unroll
        for (int q = 0; q < 2; q++) {
            int j = tid + q*256;
            int idx = j;
            float2 w1 = g_tw[idx], w2 = g_tw[2*idx], w3 = g_tw[3*idx], w4 = g_tw[4*idx];
            w1.y = -w1.y; w2.y = -w2.y; w3.y = -w3.y; w4.y = -w4.y;
            float2 o8[8];
            radix8(u[q], w1, w2, w3, w4, 1.0f, o8);
            #pragma unroll
            for (int i = 0; i < 4; i++) {
                int l = j + i*512;
                float v1 = o8[i].x*(1.0f/L2) + u1[l]*d1;
                float v2 = o8[i].y*(1.0f/L2) + u2[l]*d2;
                float t1 = 0.7978845608028654f * (v1 + 0.044715f * v1*v1*v1);
                float t2 = 0.7978845608028654f * (v2 + 0.044715f * v2*v2*v2);
                y1[l] = 0.5f * v1 * (1.0f + tanhf(t1));
                y2[l] = 0.5f * v2 * (1.0f + tanhf(t2));
            }
        }
    }
}

// ---------------- FRONT: ckfft blocks (0..511) || encoder blocks (512..1023) ----------------
__global__ __launch_bounds__(512) void front_kernel(
        const float* __restrict__ x, const float* __restrict__ eb,
        const float* __restrict__ nw, const float* __restrict__ nb,
        const float* __restrict__ lre, const float* __restrict__ lim,
        const float* __restrict__ pre, const float* __restrict__ pim,
        const float* __restrict__ bre, const float* __restrict__ bim,
        const float* __restrict__ cre, const float* __restrict__ cim,
        const float* __restrict__ lstep) {
    extern __shared__ __align__(16) char dynbuf[];
    int blk = blockIdx.x;
    int tid = threadIdx.x;
    if (blk < 512) {
        // ================= ckfft branch (l-outer cauchy, R12-proven) =================
        float2* A  = (float2*)dynbuf;          // 2048
        float2* Bb = A + Lseq;                 // 2048
        __shared__ float2 slam[Nst];
        __shared__ ull sp[4][Nst][2];
        int lay = blk >> 7, h = blk & 127;
        int hh = lay*Hd + h;
        if (tid < Nst) {
            int idx = hh*Nst + tid;
            slam[tid] = make_float2(lre[idx], lim[idx]);
            float2 P  = make_float2(pre[idx], pim[idx]);
            float2 Bv = make_float2(bre[idx], bim[idx]);
            float2 Cc = make_float2(cre[idx], -cim[idx]);
            float2 Pc = make_float2(P.x, -P.y);
            float2 vm[4];
            vm[0] = cmulf(Cc, Bv); vm[1] = cmulf(Cc, P);
            vm[2] = cmulf(Pc, Bv); vm[3] = cmulf(Pc, P);
            #pragma unroll
            for (int m = 0; m < 4; m++) {
                sp[m][tid][0] = pk(vm[m].x, vm[m].y);
                sp[m][tid][1] = pk(vm[m].y, -vm[m].x);
            }
        }
        __syncthreads();
        float ts = 2.0f / __expf(lstep[hh]);
        for (int l = tid; l < Lseq; l += 512) {
            // XLA-style omega (f32 angle + sincosf; l=L/2 must NOT be exactly -1)
            float ang = -6.2831853071795864f * ((float)l / (float)Lseq);
            float s, c;
            sincosf(ang, &s, &c);
            float dpx = 1.0f + c, dpy = s;
            float dmx = 1.0f - c, dmy = -s;
            float id2 = __fdividef(1.0f, dpx*dpx + dpy*dpy);
            float gx = ts * (dmx*dpx + dmy*dpy) * id2;
            float gy = ts * (dmy*dpx - dmx*dpy) * id2;
            float c2x = 2.0f*dpx*id2, c2y = -2.0f*dpy*id2;
            ull acc[4] = {0ull, 0ull, 0ull, 0ull};
            #pragma unroll 8
            for (int n = 0; n < Nst; n++) {
                float dx = gx - slam[n].x;
                float dy = gy - slam[n].y;
                float inv = __fdividef(1.0f, dx*dx + dy*dy);
                float rx = dx*inv, ryp = dy*inv;
                ull rxx = pk(rx, rx), ryy = pk(ryp, ryp);
                #pragma unroll
                for (int m = 0; m < 4; m++)
                    acc[m] = ffma2(sp[m][n][0], rxx, ffma2(sp[m][n][1], ryy, acc[m]));
            }
            float k00x,k00y,k01x,k01y,k10x,k10y,k11x,k11y;
            upk(acc[0], k00x, k00y); upk(acc[1], k01x, k01y);
            upk(acc[2], k10x, k10y); upk(acc[3], k11x, k11y);
            float opx = 1.0f + k11x, opy = k11y;
            float oinv = __fdividef(1.0f, opx*opx + opy*opy);
            float wx = k01x*k10x - k01y*k10y;
            float wy = k01x*k10y + k01y*k10x;
            float cx = (wx*opx + wy*opy) * oinv;
            float cy = (wy*opx - wx*opy) * oinv;
            float rx2 = k00x - cx, ry2 = k00y - cy;
            A[l] = make_float2(c2x*rx2 - c2y*ry2, c2x*ry2 + c2y*rx2);
        }
        __syncthreads();
        float2* KP2 = (float2*)(g_KdP + ((size_t)lay*(Hd/2) + (h>>1))*Lseq);
        int slot = h & 1;
        for (int m = tid; m < Lseq; m += 512) {
            if (m < 1024) {
                float2 am = A[m];
                float2 ar = A[(Lseq - m) & (Lseq-1)];
                KP2[4*m + slot] = make_float2(0.5f*(am.x + ar.x), 0.5f*(am.y - ar.y));
            } else if (m == 1024) {
                g_KdN[hh] = make_float2(A[1024].x, 0.f);
            }
        }
        float2* r = fft2048_m(A, Bb, true);
        for (int m = tid; m < Lseq; m += 512) {
            float xr = r[m].x * (1.0f/Lseq);
            float2 w = g_tw[m];
            Bb[m] = make_float2(xr * w.x, xr * w.y);
        }
        float2* r2 = fft2048_m(Bb, A, false);
        for (int m = tid; m < 1024; m += 512)
            KP2[4*m + 2 + slot] = r2[m];
    } else {
        // ================= encoder branch (512 threads, 32 rows) =================
        float* xs   = (float*)dynbuf;                       // [32][64]
        ull*   zs2b = (ull*)(dynbuf + 8192);                // [64][17]
        float* tile = (float*)(dynbuf + 8192 + 8704);       // [32][129]
        int row0 = (blk - 512) * 32;
        int b = row0 >> 11, l0 = row0 & 2047;
        for (int idx = tid; idx < 32*INF; idx += 512)
            xs[idx] = x[(size_t)(row0 + (idx >> 6))*INF + (idx & 63)];
        __syncthreads();
        for (int idx = tid; idx < INF*16; idx += 512) {
            int p = idx >> 6, k = idx & 63;
            zs2b[k*17 + p] = pk(xs[(2*p)*INF + k], xs[(2*p+1)*INF + k]);
        }
        __syncthreads();
        int c = tid & 127, quar = tid >> 7;   // 0..3
        int p0 = quar * 4;
        ull acc[4];
        {
            float bv = eb[c];
            ull bp = pk(bv, bv);
            #pragma unroll
            for (int p = 0; p < 4; p++) acc[p] = bp;
        }
        #pragma unroll 4
        for (int k = 0; k < INF; k++) {
            float wv = g_encWT[k*Hd + c];
            ull wp = pk(wv, wv);
            #pragma unroll
            for (int p = 0; p < 4; p++) acc[p] = ffma2(zs2b[k*17 + p0 + p], wp, acc[p]);
        }
        #pragma unroll
        for (int p = 0; p < 4; p++) {
            float h0v, h1v;
            upk(acc[p], h0v, h1v);
            int ra = 2*(p0 + p), rb = ra + 1;
            g_h[(size_t)(row0 + ra)*Hd + c] = h0v;
            g_h[(size_t)(row0 + rb)*Hd + c] = h1v;
            tile[ra*129 + c] = h0v; tile[rb*129 + c] = h1v;
        }
        __syncthreads();
        int warp = tid >> 5, lane = tid & 31;
        #pragma unroll
        for (int rr = 0; rr < 2; rr++) {
            int l = warp*2 + rr;   // 16 warps x 2 = 32 rows
            float v[4]; float sum = 0.f;
            #pragma unroll
            for (int i = 0; i < 4; i++) { v[i] = tile[l*129 + lane + 32*i]; sum += v[i]; }
            #pragma unroll
            for (int o = 16; o; o >>= 1) sum += __shfl_xor_sync(0xffffffffu, sum, o);
            float mu = sum * (1.0f/Hd);
            float var = 0.f;
            #pragma unroll
            for (int i = 0; i < 4; i++) { float t = v[i]-mu; var += t*t; }
            #pragma unroll
            for (int o = 16; o; o >>= 1) var += __shfl_xor_sync(0xffffffffu, var, o);
            float rstd = rsqrtf(var * (1.0f/Hd) + 1e-5f);
            #pragma unroll
            for (int i = 0; i < 4; i++) {
                int cc = lane + 32*i;
                tile[l*129 + cc] = (v[i]-mu)*rstd*nw[cc] + nb[cc];
            }
        }
        __syncthreads();
        for (int idx = tid; idx < 32*Hd; idx += 512) {
            int hh = idx >> 5, l = idx & 31;
            g_hnT[((size_t)(b*Hd + hh))*Lseq + l0 + l] = tile[l*129 + hh];
        }
    }
}

// ---------------- gated MLP + residual + fused next-LN / fused decoder ----------------
__global__ __launch_bounds__(512) void mlp_kernel(const float* __restrict__ b1,
                                                  const float* __restrict__ b2,
                                                  const float* __restrict__ nw,
                                                  const float* __restrict__ nb,
                                                  const float* __restrict__ dec_bias,
                                                  float* __restrict__ out,
                                                  int lay, int do_ln) {
    const float* __restrict__ w1T = g_w1T + lay*Hd*Hd;
    const float* __restrict__ w2T = g_w2T + lay*Hd*Hd;
    __shared__ __align__(16) unsigned char smbuf[64*129*4];
    ull   (*zs2)[32]  = reinterpret_cast<ull(*)[32]>(smbuf);
    float (*tile)[129] = reinterpret_cast<float(*)[129]>(smbuf);
    int row0 = blockIdx.x * 64;
    int b = row0 >> 11, l0 = row0 & 2047;
    int tid = threadIdx.x;
    int c = tid & 127, grp = tid >> 7;
    for (int idx = tid; idx < Hd*32; idx += 512) {
        int k = idx >> 5, p = idx & 31;
        float2 v = *(const float2*)&g_yT[((size_t)(b*Hd + k))*Lseq + l0 + 2*p];
        zs2[k][p] = pk(v.x, v.y);
    }
    __syncthreads();
    int p0 = grp * 8;
    ull acc1[8], acc2[8];
    {
        float b1v = b1[c], b2v = b2[c];
        ull p1 = pk(b1v, b1v), p2 = pk(b2v, b2v);
        #pragma unroll
        for (int p = 0; p < 8; p++) { acc1[p] = p1; acc2[p] = p2; }
    }
    #pragma unroll 2
    for (int k = 0; k < Hd; k++) {
        float w1v = w1T[k*Hd + c];
        float w2v = w2T[k*Hd + c];
        ull w1p = pk(w1v, w1v), w2p = pk(w2v, w2v);
        #pragma unroll
        for (int p = 0; p < 8; p++) {
            ull zp = zs2[k][p0 + p];
            acc1[p] = ffma2(zp, w1p, acc1[p]);
            acc2[p] = ffma2(zp, w2p, acc2[p]);
        }
    }
    __syncthreads();   // zs2 dead; tile may now alias it
    #pragma unroll
    for (int p = 0; p < 8; p++) {
        float o0, o1, g0, g1;
        upk(acc1[p], o0, o1);
        upk(acc2[p], g0, g1);
        int ra = 2*(p0 + p), rb = ra + 1;
        size_t ia = (size_t)(row0 + ra)*Hd + c;
        size_t ib = (size_t)(row0 + rb)*Hd + c;
        float ha = g_h[ia] + o0 / (1.0f + __expf(-g0));
        float hb = g_h[ib] + o1 / (1.0f + __expf(-g1));
        if (do_ln) { g_h[ia] = ha; g_h[ib] = hb; }   // last layer: h only needed for dec below
        tile[ra][c] = ha; tile[rb][c] = hb;
    }
    __syncthreads();
    if (do_ln) {
        int warp = tid >> 5, lane = tid & 31;
        #pragma unroll
        for (int rr = 0; rr < 4; rr++) {
            int l = warp*4 + rr;
            float v[4]; float sum = 0.f;
            #pragma unroll
            for (int i = 0; i < 4; i++) { v[i] = tile[l][lane + 32*i]; sum += v[i]; }
            #pragma unroll
            for (int o = 16; o; o >>= 1) sum += __shfl_xor_sync(0xffffffffu, sum, o);
            float mu = sum * (1.0f/Hd);
            float var = 0.f;
            #pragma unroll
            for (int i = 0; i < 4; i++) { float t = v[i]-mu; var += t*t; }
            #pragma unroll
            for (int o = 16; o; o >>= 1) var += __shfl_xor_sync(0xffffffffu, var, o);
            float rstd = rsqrtf(var * (1.0f/Hd) + 1e-5f);
            #pragma unroll
            for (int i = 0; i < 4; i++) {
                int cc = lane + 32*i;
                tile[l][cc] = (v[i]-mu)*rstd*nw[cc] + nb[cc];
            }
        }
        __syncthreads();
        for (int idx = tid; idx < 64*Hd; idx += 512) {
            int hh = idx >> 6, l = idx & 63;
            g_hnT[((size_t)(b*Hd + hh))*Lseq + l0 + l] = tile[l][hh];
        }
    } else {
        // fused decoder: out[row][o] = sum_k tile[row][k] * decWT[k][o] + dec_b[o]
        int o = tid & 63, rg = tid >> 6;   // 8 groups x 8 rows (4 pairs)
        ull acc[4];
        {
            float bv = dec_bias[o];
            ull bp = pk(bv, bv);
            #pragma unroll
            for (int p = 0; p < 4; p++) acc[p] = bp;
        }
        #pragma unroll 2
        for (int k = 0; k < Hd; k++) {
            float wv = g_decWT[k*OUTF + o];
            ull wp = pk(wv, wv);
            #pragma unroll
            for (int p = 0; p < 4; p++) {
                int r = rg*8 + 2*p;
                acc[p] = ffma2(pk(tile[r][k], tile[r+1][k]), wp, acc[p]);
            }
        }
        #pragma unroll
        for (int p = 0; p < 4; p++) {
            float y0, y1;
            upk(acc[p], y0, y1);
            int r = rg*8 + 2*p;
            out[(size_t)(row0 + r)*OUTF + o]     = y0;
            out[(size_t)(row0 + r + 1)*OUTF + o] = y1;
        }
    }
}

// ---------------- launch ----------------
extern "C" void kernel_launch(void* const* d_in, const int* in_sizes, int n_in,
                              void* d_out, int out_size) {
    const float* x       = (const float*)d_in[0];
    const float* enc_w   = (const float*)d_in[2];
    const float* enc_b   = (const float*)d_in[3];
    const float* dec_w   = (const float*)d_in[4];
    const float* dec_b   = (const float*)d_in[5];
    const float* lam_re  = (const float*)d_in[6];
    const float* lam_im  = (const float*)d_in[7];
    const float* p_re    = (const float*)d_in[8];
    const float* p_im    = (const float*)d_in[9];
    const float* b_re    = (const float*)d_in[10];
    const float* b_im    = (const float*)d_in[11];
    const float* c_re    = (const float*)d_in[12];
    const float* c_im    = (const float*)d_in[13];
    const float* dvec    = (const float*)d_in[14];
    const float* logstep = (const float*)d_in[15];
    const float* norm_w  = (const float*)d_in[16];
    const float* norm_b  = (const float*)d_in[17];
    const float* w1      = (const float*)d_in[18];
    const float* b1      = (const float*)d_in[19];
    const float* w2      = (const float*)d_in[20];
    const float* b2      = (const float*)d_in[21];
    float* out = (float*)d_out;

    int smem_front = 8192 + 8704 + 32*129*4 + 128;   // 33.5 KB (encoder layout is the max)
    cudaFuncSetAttribute(front_kernel, cudaFuncAttributeMaxDynamicSharedMemorySize, smem_front);

    prep_kernel<<<(NLAY*Hd*Hd + 255)/256, 256>>>(enc_w, dec_w, w1, w2);
    // ckfft (512 blocks) runs CONCURRENTLY with encoder+LN (512 blocks)
    front_kernel<<<1024, 512, smem_front>>>(x, enc_b, norm_w, norm_b,
                                            lam_re, lam_im, p_re, p_im,
                                            b_re, b_im, c_re, c_im, logstep);
    for (int i = 0; i < NLAY; i++) {
        conv_kernel<<<Bsz*Hd/2, 256>>>(dvec + i*Hd, i);
        int last = (i == NLAY-1);
        mlp_kernel<<<ROWS/64, 512>>>(b1 + i*Hd, b2 + i*Hd,
                                     norm_w + (last ? 0 : (i+1)*Hd),
                                     norm_b + (last ? 0 : (i+1)*Hd),
                                     dec_b, out,
                                     i, last ? 0 : 1);
    }
}

// round 16
// speedup vs baseline: 1.1389x; 1.0167x over previous
#include <cuda_runtime.h>
#include <math.h>

#define Bsz 8
#define Lseq 2048
#define INF 64
#define OUTF 64
#define Hd 128
#define Nst 64
#define NLAY 4
#define L2 4096
#define ROWS (Bsz*Lseq)

typedef unsigned long long ull;

// ---------------- persistent scratch ----------------
__device__ float  g_h  [ROWS*Hd];          // activations (B,L,H)
__device__ float  g_hnT[Bsz*Hd*Lseq];      // layernormed, transposed (B,H,L)
__device__ float  g_yT [Bsz*Hd*Lseq];      // gelu(conv output), transposed (B,H,L)
__device__ float4 g_KdP[NLAY*(Hd/2)*Lseq]; // spectra f<2048, channel pairs interleaved (K1,K2)
__device__ float2 g_KdN[NLAY*Hd];          // spectrum bin 2048 per channel
__device__ float2 g_tw [L2/2];             // twiddles W_4096^m, m < 2048
__device__ float  g_w1T[NLAY*Hd*Hd];       // transposed weights [k][c]
__device__ float  g_w2T[NLAY*Hd*Hd];
__device__ float  g_encWT[INF*Hd];
__device__ float  g_decWT[Hd*OUTF];

__device__ __forceinline__ float2 cmulf(float2 a, float2 b) {
    return make_float2(a.x*b.x - a.y*b.y, a.x*b.y + a.y*b.x);
}
__device__ __forceinline__ float2 caddf(float2 a, float2 b){ return make_float2(a.x+b.x, a.y+b.y); }
__device__ __forceinline__ float2 csubf(float2 a, float2 b){ return make_float2(a.x-b.x, a.y-b.y); }
__device__ __forceinline__ float2 addi(float2 a, float2 d, float sgn) {
    return make_float2(a.x - sgn*d.y, a.y + sgn*d.x);
}
__device__ __forceinline__ ull pk(float x, float y) {
    ull r; asm("mov.b64 %0, {%1, %2};" : "=l"(r) : "f"(x), "f"(y)); return r;
}
__device__ __forceinline__ void upk(ull p, float& x, float& y) {
    asm("mov.b64 {%0, %1}, %2;" : "=f"(x), "=f"(y) : "l"(p));
}
__device__ __forceinline__ ull ffma2(ull a, ull b, ull c) {
    ull d; asm("fma.rn.f32x2 %0, %1, %2, %3;" : "=l"(d) : "l"(a), "l"(b), "l"(c)); return d;
}

// ---------------- prep: twiddles + weight transposes ----------------
__global__ void prep_kernel(const float* __restrict__ enc_w, const float* __restrict__ dec_w,
                            const float* __restrict__ w1, const float* __restrict__ w2) {
    int tid = blockIdx.x * 256 + threadIdx.x;
    if (tid < L2/2) {
        float s, c;
        sincospif(-(float)tid / 2048.0f, &s, &c);
        g_tw[tid] = make_float2(c, s);
    }
    if (tid < INF*Hd) { int k = tid >> 7, c = tid & 127; g_encWT[tid] = enc_w[c*INF + k]; }
    if (tid < Hd*OUTF) { int k = tid >> 6, o = tid & 63; g_decWT[tid] = dec_w[o*Hd + k]; }
    if (tid < NLAY*Hd*Hd) {
        int lay = tid >> 14, r = tid & 16383, k = r >> 7, c = r & 127;
        g_w1T[tid] = w1[lay*Hd*Hd + c*Hd + k];
        g_w2T[tid] = w2[lay*Hd*Hd + c*Hd + k];
    }
}

// ---------------- radix-8 butterfly ----------------
__device__ __forceinline__ void radix8(const float2 u[8],
                                       float2 w1, float2 w2, float2 w3, float2 w4,
                                       float sgnF, float2 out[8]) {
    const float cc = 0.70710678118654752f;
    float2 w5 = cmulf(w4, w1);
    float2 w6 = cmulf(w3, w3);
    float2 w7 = cmulf(w4, w3);
    float2 t0 = u[0];
    float2 t1 = cmulf(w1, u[1]);
    float2 t2 = cmulf(w2, u[2]);
    float2 t3 = cmulf(w3, u[3]);
    float2 t4 = cmulf(w4, u[4]);
    float2 t5 = cmulf(w5, u[5]);
    float2 t6 = cmulf(w6, u[6]);
    float2 t7 = cmulf(w7, u[7]);
    float2 s04 = caddf(t0, t4), d04 = csubf(t0, t4);
    float2 s26 = caddf(t2, t6), d26 = csubf(t2, t6);
    float2 s15 = caddf(t1, t5), d15 = csubf(t1, t5);
    float2 s37 = caddf(t3, t7), d37 = csubf(t3, t7);
    float2 E0 = caddf(s04, s26), E2 = csubf(s04, s26);
    float2 E1 = addi(d04, d26, sgnF), E3 = addi(d04, d26, -sgnF);
    float2 O0 = caddf(s15, s37), O2 = csubf(s15, s37);
    float2 O1 = addi(d15, d37, sgnF), O3 = addi(d15, d37, -sgnF);
    float2 W81 = make_float2(cc,  sgnF*cc);
    float2 W83 = make_float2(-cc, sgnF*cc);
    float2 p1 = cmulf(O1, W81);
    float2 p2 = make_float2(-sgnF*O2.y, sgnF*O2.x);
    float2 p3 = cmulf(O3, W83);
    out[0] = caddf(E0, O0); out[4] = csubf(E0, O0);
    out[1] = caddf(E1, p1); out[5] = csubf(E1, p1);
    out[2] = caddf(E2, p2); out[6] = csubf(E2, p2);
    out[3] = caddf(E3, p3); out[7] = csubf(E3, p3);
}

// ---------------- 2048-pt Stockham FFT (double-buffered; ckfft only) ----------------
__device__ float2* fft2048_m(float2* a, float2* b, bool inverse) {
    float2* src = a; float2* dst = b;
    const float sgnF = inverse ? 1.0f : -1.0f;
    __syncthreads();
    for (int j = threadIdx.x; j < 512; j += blockDim.x) {
        float2 u0 = src[j], u1 = src[j+512], u2 = src[j+1024], u3 = src[j+1536];
        float2 a02 = caddf(u0, u2), s02 = csubf(u0, u2);
        float2 a13 = caddf(u1, u3), s13 = csubf(u1, u3);
        int o = j << 2;
        dst[o  ] = caddf(a02, a13);
        dst[o+1] = addi(s02, s13, sgnF);
        dst[o+2] = csubf(a02, a13);
        dst[o+3] = addi(s02, s13, -sgnF);
    }
    { float2* tmp = src; src = dst; dst = tmp; }
    int L = 4, mult = 128;
    #pragma unroll
    for (int t = 0; t < 3; t++) {
        __syncthreads();
        for (int j = threadIdx.x; j < 256; j += blockDim.x) {
            int k = j & (L - 1);
            int blk = j >> (2 + 3*t);
            float2 u[8];
            #pragma unroll
            for (int i = 0; i < 8; i++) u[i] = src[j + i*256];
            int idx = k * mult;
            float2 w1 = g_tw[idx], w2 = g_tw[2*idx], w3 = g_tw[3*idx], w4 = g_tw[4*idx];
            if (inverse) { w1.y = -w1.y; w2.y = -w2.y; w3.y = -w3.y; w4.y = -w4.y; }
            float2 o8[8];
            radix8(u, w1, w2, w3, w4, sgnF, o8);
            int o = (blk << 3)*L + k;
            #pragma unroll
            for (int i = 0; i < 8; i++) dst[o + i*L] = o8[i];
        }
        { float2* tmp = src; src = dst; dst = tmp; }
        L <<= 3; mult >>= 3;
    }
    __syncthreads();
    return src;
}

// ---------------- one in-place radix-8 stage (4096 pts, 256 threads) ----------------
__device__ __forceinline__ void stage_ip(float2* A, int t, int L, int mult,
                                         float sgnF, bool conj) {
    float2 u[2][8];
    #pragma unroll
    for (int q = 0; q < 2; q++) {
        int j = threadIdx.x + q*256;
        #pragma unroll
        for (int i = 0; i < 8; i++) u[q][i] = A[j + i*512];
    }
    __syncthreads();
    #pragma unroll
    for (int q = 0; q < 2; q++) {
        int j = threadIdx.x + q*256;
        int k = j & (L - 1);
        int blkq = j >> (3*t);
        int idx = k * mult;
        float2 w1 = g_tw[idx], w2 = g_tw[2*idx], w3 = g_tw[3*idx], w4 = g_tw[4*idx];
        if (conj) { w1.y = -w1.y; w2.y = -w2.y; w3.y = -w3.y; w4.y = -w4.y; }
        float2 o8[8];
        radix8(u[q], w1, w2, w3, w4, sgnF, o8);
        int o = (blkq << (3*t + 3)) + k;
        #pragma unroll
        for (int i = 0; i < 8; i++) A[o + i*L] = o8[i];
    }
    __syncthreads();
}

// ---------------- FFT causal conv (R14 winner, unchanged) ----------------
__global__ __launch_bounds__(256, 4) void conv_kernel(const float* __restrict__ dvec, int lay) {
    __shared__ float2 A[L2];
    int blk = blockIdx.x;
    int b = blk >> 6, hp = blk & 63;
    int h0 = 2*hp;
    int tid = threadIdx.x;
    const float* u1 = g_hnT + ((size_t)b*Hd + h0)*Lseq;
    const float* u2 = u1 + Lseq;
    const float2 ONE = make_float2(1.f, 0.f);

    #pragma unroll
    for (int q = 0; q < 2; q++) {
        int j = tid + q*256;
        float2 u[8], o8[8];
        #pragma unroll
        for (int i = 0; i < 4; i++) u[i] = make_float2(u1[j + i*512], u2[j + i*512]);
        #pragma unroll
        for (int i = 4; i < 8; i++) u[i] = make_float2(0.f, 0.f);
        radix8(u, ONE, ONE, ONE, ONE, -1.0f, o8);
        #pragma unroll
        for (int i = 0; i < 8; i++) A[(j << 3) + i] = o8[i];
    }
    __syncthreads();
    stage_ip(A, 1, 8,   64, -1.0f, false);
    stage_ip(A, 2, 64,  8,  -1.0f, false);
    stage_ip(A, 3, 512, 1,  -1.0f, false);

    const float4* KP = g_KdP + ((size_t)lay*(Hd/2) + hp)*Lseq;
    #pragma unroll
    for (int s = 0; s < 8; s++) {
        int f  = tid + s*256;
        int fr = (L2 - f) & (L2-1);
        float2 zf = A[f], zr = A[fr];
        float4 K = KP[f];
        float2 K1 = make_float2(K.x, K.y), K2 = make_float2(K.z, K.w);
        float2 U1 = make_float2(0.5f*(zf.x + zr.x),  0.5f*(zf.y - zr.y));
        float2 U2 = make_float2(0.5f*(zf.y + zr.y), -0.5f*(zf.x - zr.x));
        float2 Y1 = cmulf(U1, K1);
        float2 Y2 = cmulf(U2, K2);
        A[f] = make_float2(Y1.x - Y2.y, Y1.y + Y2.x);
        if (f != 0)
            A[fr] = make_float2(Y1.x + Y2.y, Y2.x - Y1.y);
        if (f == 0) {
            float2 z = A[2048];
            float2 K1n = g_KdN[lay*Hd + h0];
            float2 K2n = g_KdN[lay*Hd + h0 + 1];
            float2 Y1n = make_float2(z.x*K1n.x, z.x*K1n.y);
            float2 Y2n = make_float2(z.y*K2n.x, z.y*K2n.y);
            A[2048] = make_float2(Y1n.x - Y2n.y, Y1n.y + Y2n.x);
        }
    }
    __syncthreads();

    {
        float2 u[2][8];
        #pragma unroll
        for (int q = 0; q < 2; q++) {
            int j = tid + q*256;
            #pragma unroll
            for (int i = 0; i < 8; i++) u[q][i] = A[j + i*512];
        }
        __syncthreads();
        #pragma unroll
        for (int q = 0; q < 2; q++) {
            int j = tid + q*256;
            float2 o8[8];
            radix8(u[q], ONE, ONE, ONE, ONE, 1.0f, o8);
            #pragma unroll
            for (int i = 0; i < 8; i++) A[(j << 3) + i] = o8[i];
        }
        __syncthreads();
    }
    stage_ip(A, 1, 8,  64, 1.0f, true);
    stage_ip(A, 2, 64, 8,  1.0f, true);
    {
        float d1 = dvec[h0], d2 = dvec[h0+1];
        float* y1 = g_yT + ((size_t)b*Hd + h0)*Lseq;
        float* y2 = y1 + Lseq;
        float2 u[2][8];
        #pragma unroll
        for (int q = 0; q < 2; q++) {
            int j = tid + q*256;
            #pragma unroll
            for (int i = 0; i < 8; i++) u[q][i] = A[j + i*512];
        }
        #pragma unroll
        for (int q = 0; q < 2; q++) {
            int j = tid + q*256;
            int idx = j;
            float2 w1 = g_tw[idx], w2 = g_tw[2*idx], w3 = g_tw[3*idx], w4 = g_tw[4*idx];
            w1.y = -w1.y; w2.y = -w2.y; w3.y = -w3.y; w4.y = -w4.y;
            float2 o8[8];
            radix8(u[q], w1, w2, w3, w4, 1.0f, o8);
            #pragma unroll
            for (int i = 0; i < 4; i++) {
                int l = j + i*512;
                float v1 = o8[i].x*(1.0f/L2) + u1[l]*d1;
                float v2 = o8[i].y*(1.0f/L2) + u2[l]*d2;
                float t1 = 0.7978845608028654f * (v1 + 0.044715f * v1*v1*v1);
                float t2 = 0.7978845608028654f * (v2 + 0.044715f * v2*v2*v2);
                y1[l] = 0.5f * v1 * (1.0f + tanhf(t1));
                y2[l] = 0.5f * v2 * (1.0f + tanhf(t2));
            }
        }
    }
}

// ---------------- FRONT: ckfft blocks (0..511) || encoder blocks (512..1023) ----------------
__global__ __launch_bounds__(512) void front_kernel(
        const float* __restrict__ x, const float* __restrict__ eb,
        const float* __restrict__ nw, const float* __restrict__ nb,
        const float* __restrict__ lre, const float* __restrict__ lim,
        const float* __restrict__ pre, const float* __restrict__ pim,
        const float* __restrict__ bre, const float* __restrict__ bim,
        const float* __restrict__ cre, const float* __restrict__ cim,
        const float* __restrict__ lstep) {
    extern __shared__ __align__(16) char dynbuf[];
    int blk = blockIdx.x;
    int tid = threadIdx.x;
    if (blk < 512) {
        float2* A  = (float2*)dynbuf;
        float2* Bb = A + Lseq;
        __shared__ float2 slam[Nst];
        __shared__ ull sp[4][Nst][2];
        int lay = blk >> 7, h = blk & 127;
        int hh = lay*Hd + h;
        if (tid < Nst) {
            int idx = hh*Nst + tid;
            slam[tid] = make_float2(lre[idx], lim[idx]);
            float2 P  = make_float2(pre[idx], pim[idx]);
            float2 Bv = make_float2(bre[idx], bim[idx]);
            float2 Cc = make_float2(cre[idx], -cim[idx]);
            float2 Pc = make_float2(P.x, -P.y);
            float2 vm[4];
            vm[0] = cmulf(Cc, Bv); vm[1] = cmulf(Cc, P);
            vm[2] = cmulf(Pc, Bv); vm[3] = cmulf(Pc, P);
            #pragma unroll
            for (int m = 0; m < 4; m++) {
                sp[m][tid][0] = pk(vm[m].x, vm[m].y);
                sp[m][tid][1] = pk(vm[m].y, -vm[m].x);
            }
        }
        __syncthreads();
        float ts = 2.0f / __expf(lstep[hh]);
        for (int l = tid; l < Lseq; l += 512) {
            // XLA-style omega (f32 angle + sincosf; l=L/2 must NOT be exactly -1)
            float ang = -6.2831853071795864f * ((float)l / (float)Lseq);
            float s, c;
            sincosf(ang, &s, &c);
            float dpx = 1.0f + c, dpy = s;
            float dmx = 1.0f - c, dmy = -s;
            float id2 = __fdividef(1.0f, dpx*dpx + dpy*dpy);
            float gx = ts * (dmx*dpx + dmy*dpy) * id2;
            float gy = ts * (dmy*dpx - dmx*dpy) * id2;
            float c2x = 2.0f*dpx*id2, c2y = -2.0f*dpy*id2;
            ull acc[4] = {0ull, 0ull, 0ull, 0ull};
            #pragma unroll 8
            for (int n = 0; n < Nst; n++) {
                float dx = gx - slam[n].x;
                float dy = gy - slam[n].y;
                float inv = __fdividef(1.0f, dx*dx + dy*dy);
                float rx = dx*inv, ryp = dy*inv;
                ull rxx = pk(rx, rx), ryy = pk(ryp, ryp);
                #pragma unroll
                for (int m = 0; m < 4; m++)
                    acc[m] = ffma2(sp[m][n][0], rxx, ffma2(sp[m][n][1], ryy, acc[m]));
            }
            float k00x,k00y,k01x,k01y,k10x,k10y,k11x,k11y;
            upk(acc[0], k00x, k00y); upk(acc[1], k01x, k01y);
            upk(acc[2], k10x, k10y); upk(acc[3], k11x, k11y);
            float opx = 1.0f + k11x, opy = k11y;
            float oinv = __fdividef(1.0f, opx*opx + opy*opy);
            float wx = k01x*k10x - k01y*k10y;
            float wy = k01x*k10y + k01y*k10x;
            float cx = (wx*opx + wy*opy) * oinv;
            float cy = (wy*opx - wx*opy) * oinv;
            float rx2 = k00x - cx, ry2 = k00y - cy;
            A[l] = make_float2(c2x*rx2 - c2y*ry2, c2x*ry2 + c2y*rx2);
        }
        __syncthreads();
        float2* KP2 = (float2*)(g_KdP + ((size_t)lay*(Hd/2) + (h>>1))*Lseq);
        int slot = h & 1;
        for (int m = tid; m < Lseq; m += 512) {
            if (m < 1024) {
                float2 am = A[m];
                float2 ar = A[(Lseq - m) & (Lseq-1)];
                KP2[4*m + slot] = make_float2(0.5f*(am.x + ar.x), 0.5f*(am.y - ar.y));
            } else if (m == 1024) {
                g_KdN[hh] = make_float2(A[1024].x, 0.f);
            }
        }
        float2* r = fft2048_m(A, Bb, true);
        for (int m = tid; m < Lseq; m += 512) {
            float xr = r[m].x * (1.0f/Lseq);
            float2 w = g_tw[m];
            Bb[m] = make_float2(xr * w.x, xr * w.y);
        }
        float2* r2 = fft2048_m(Bb, A, false);
        for (int m = tid; m < 1024; m += 512)
            KP2[4*m + 2 + slot] = r2[m];
    } else {
        float* xs   = (float*)dynbuf;
        ull*   zs2b = (ull*)(dynbuf + 8192);
        float* tile = (float*)(dynbuf + 8192 + 8704);
        int row0 = (blk - 512) * 32;
        int b = row0 >> 11, l0 = row0 & 2047;
        for (int idx = tid; idx < 32*INF; idx += 512)
            xs[idx] = x[(size_t)(row0 + (idx >> 6))*INF + (idx & 63)];
        __syncthreads();
        for (int idx = tid; idx < INF*16; idx += 512) {
            int p = idx >> 6, k = idx & 63;
            zs2b[k*17 + p] = pk(xs[(2*p)*INF + k], xs[(2*p+1)*INF + k]);
        }
        __syncthreads();
        int c = tid & 127, quar = tid >> 7;
        int p0 = quar * 4;
        ull acc[4];
        {
            float bv = eb[c];
            ull bp = pk(bv, bv);
            #pragma unroll
            for (int p = 0; p < 4; p++) acc[p] = bp;
        }
        #pragma unroll 4
        for (int k = 0; k < INF; k++) {
            float wv = g_encWT[k*Hd + c];
            ull wp = pk(wv, wv);
            #pragma unroll
            for (int p = 0; p < 4; p++) acc[p] = ffma2(zs2b[k*17 + p0 + p], wp, acc[p]);
        }
        #pragma unroll
        for (int p = 0; p < 4; p++) {
            float h0v, h1v;
            upk(acc[p], h0v, h1v);
            int ra = 2*(p0 + p), rb = ra + 1;
            g_h[(size_t)(row0 + ra)*Hd + c] = h0v;
            g_h[(size_t)(row0 + rb)*Hd + c] = h1v;
            tile[ra*129 + c] = h0v; tile[rb*129 + c] = h1v;
        }
        __syncthreads();
        int warp = tid >> 5, lane = tid & 31;
        #pragma unroll
        for (int rr = 0; rr < 2; rr++) {
            int l = warp*2 + rr;
            float v[4]; float sum = 0.f;
            #pragma unroll
            for (int i = 0; i < 4; i++) { v[i] = tile[l*129 + lane + 32*i]; sum += v[i]; }
            #pragma unroll
            for (int o = 16; o; o >>= 1) sum += __shfl_xor_sync(0xffffffffu, sum, o);
            float mu = sum * (1.0f/Hd);
            float var = 0.f;
            #pragma unroll
            for (int i = 0; i < 4; i++) { float t = v[i]-mu; var += t*t; }
            #pragma unroll
            for (int o = 16; o; o >>= 1) var += __shfl_xor_sync(0xffffffffu, var, o);
            float rstd = rsqrtf(var * (1.0f/Hd) + 1e-5f);
            #pragma unroll
            for (int i = 0; i < 4; i++) {
                int cc = lane + 32*i;
                tile[l*129 + cc] = (v[i]-mu)*rstd*nw[cc] + nb[cc];
            }
        }
        __syncthreads();
        for (int idx = tid; idx < 32*Hd; idx += 512) {
            int hh = idx >> 5, l = idx & 31;
            g_hnT[((size_t)(b*Hd + hh))*Lseq + l0 + l] = tile[l*129 + hh];
        }
    }
}

// ---------------- gated MLP + residual + fused next-LN / fused decoder ----------------
__global__ __launch_bounds__(512, 2) void mlp_kernel(const float* __restrict__ b1,
                                                     const float* __restrict__ b2,
                                                     const float* __restrict__ nw,
                                                     const float* __restrict__ nb,
                                                     const float* __restrict__ dec_bias,
                                                     float* __restrict__ out,
                                                     int lay, int do_ln) {
    const float* __restrict__ w1T = g_w1T + lay*Hd*Hd;
    const float* __restrict__ w2T = g_w2T + lay*Hd*Hd;
    __shared__ __align__(16) unsigned char smbuf[64*129*4];
    ull   (*zs2)[32]  = reinterpret_cast<ull(*)[32]>(smbuf);
    float (*tile)[129] = reinterpret_cast<float(*)[129]>(smbuf);
    int row0 = blockIdx.x * 64;
    int b = row0 >> 11, l0 = row0 & 2047;
    int tid = threadIdx.x;
    int c = tid & 127, grp = tid >> 7;
    for (int idx = tid; idx < Hd*32; idx += 512) {
        int k = idx >> 5, p = idx & 31;
        float2 v = *(const float2*)&g_yT[((size_t)(b*Hd + k))*Lseq + l0 + 2*p];
        zs2[k][p] = pk(v.x, v.y);
    }
    __syncthreads();
    int p0 = grp * 8;
    ull acc1[8], acc2[8];
    {
        float b1v = b1[c], b2v = b2[c];
        ull p1 = pk(b1v, b1v), p2 = pk(b2v, b2v);
        #pragma unroll
        for (int p = 0; p < 8; p++) { acc1[p] = p1; acc2[p] = p2; }
    }
    // GEMM loop: batched LDS.128 z loads + __ldg weights, loads hoisted per iteration
    #pragma unroll 2
    for (int k = 0; k < Hd; k++) {
        float w1v = __ldg(&w1T[k*Hd + c]);
        float w2v = __ldg(&w2T[k*Hd + c]);
        const float4* z4 = reinterpret_cast<const float4*>(&zs2[k][p0]);
        float4 za = z4[0], zb = z4[1], zc = z4[2], zd = z4[3];
        ull w1p = pk(w1v, w1v), w2p = pk(w2v, w2v);
        ull zp[8];
        zp[0] = pk(za.x, za.y); zp[1] = pk(za.z, za.w);
        zp[2] = pk(zb.x, zb.y); zp[3] = pk(zb.z, zb.w);
        zp[4] = pk(zc.x, zc.y); zp[5] = pk(zc.z, zc.w);
        zp[6] = pk(zd.x, zd.y); zp[7] = pk(zd.z, zd.w);
        #pragma unroll
        for (int p = 0; p < 8; p++) {
            acc1[p] = ffma2(zp[p], w1p, acc1[p]);
            acc2[p] = ffma2(zp[p], w2p, acc2[p]);
        }
    }
    __syncthreads();   // zs2 dead; tile may now alias it
    #pragma unroll
    for (int p = 0; p < 8; p++) {
        float o0, o1, g0, g1;
        upk(acc1[p], o0, o1);
        upk(acc2[p], g0, g1);
        int ra = 2*(p0 + p), rb = ra + 1;
        size_t ia = (size_t)(row0 + ra)*Hd + c;
        size_t ib = (size_t)(row0 + rb)*Hd + c;
        float ha = g_h[ia] + o0 / (1.0f + __expf(-g0));
        float hb = g_h[ib] + o1 / (1.0f + __expf(-g1));
        if (do_ln) { g_h[ia] = ha; g_h[ib] = hb; }
        tile[ra][c] = ha; tile[rb][c] = hb;
    }
    __syncthreads();
    if (do_ln) {
        int warp = tid >> 5, lane = tid & 31;
        #pragma unroll
        for (int rr = 0; rr < 4; rr++) {
            int l = warp*4 + rr;
            float v[4]; float sum = 0.f;
            #pragma unroll
            for (int i = 0; i < 4; i++) { v[i] = tile[l][lane + 32*i]; sum += v[i]; }
            #pragma unroll
            for (int o = 16; o; o >>= 1) sum += __shfl_xor_sync(0xffffffffu, sum, o);
            float mu = sum * (1.0f/Hd);
            float var = 0.f;
            #pragma unroll
            for (int i = 0; i < 4; i++) { float t = v[i]-mu; var += t*t; }
            #pragma unroll
            for (int o = 16; o; o >>= 1) var += __shfl_xor_sync(0xffffffffu, var, o);
            float rstd = rsqrtf(var * (1.0f/Hd) + 1e-5f);
            #pragma unroll
            for (int i = 0; i < 4; i++) {
                int cc = lane + 32*i;
                tile[l][cc] = (v[i]-mu)*rstd*nw[cc] + nb[cc];
            }
        }
        __syncthreads();
        for (int idx = tid; idx < 64*Hd; idx += 512) {
            int hh = idx >> 6, l = idx & 63;
            g_hnT[((size_t)(b*Hd + hh))*Lseq + l0 + l] = tile[l][hh];
        }
    } else {
        int o = tid & 63, rg = tid >> 6;
        ull acc[4];
        {
            float bv = dec_bias[o];
            ull bp = pk(bv, bv);
            #pragma unroll
            for (int p = 0; p < 4; p++) acc[p] = bp;
        }
        #pragma unroll 2
        for (int k = 0; k < Hd; k++) {
            float wv = __ldg(&g_decWT[k*OUTF + o]);
            ull wp = pk(wv, wv);
            #pragma unroll
            for (int p = 0; p < 4; p++) {
                int r = rg*8 + 2*p;
                acc[p] = ffma2(pk(tile[r][k], tile[r+1][k]), wp, acc[p]);
            }
        }
        #pragma unroll
        for (int p = 0; p < 4; p++) {
            float y0, y1;
            upk(acc[p], y0, y1);
            int r = rg*8 + 2*p;
            out[(size_t)(row0 + r)*OUTF + o]     = y0;
            out[(size_t)(row0 + r + 1)*OUTF + o] = y1;
        }
    }
}

// ---------------- launch ----------------
extern "C" void kernel_launch(void* const* d_in, const int* in_sizes, int n_in,
                              void* d_out, int out_size) {
    const float* x       = (const float*)d_in[0];
    const float* enc_w   = (const float*)d_in[2];
    const float* enc_b   = (const float*)d_in[3];
    const float* dec_w   = (const float*)d_in[4];
    const float* dec_b   = (const float*)d_in[5];
    const float* lam_re  = (const float*)d_in[6];
    const float* lam_im  = (const float*)d_in[7];
    const float* p_re    = (const float*)d_in[8];
    const float* p_im    = (const float*)d_in[9];
    const float* b_re    = (const float*)d_in[10];
    const float* b_im    = (const float*)d_in[11];
    const float* c_re    = (const float*)d_in[12];
    const float* c_im    = (const float*)d_in[13];
    const float* dvec    = (const float*)d_in[14];
    const float* logstep = (const float*)d_in[15];
    const float* norm_w  = (const float*)d_in[16];
    const float* norm_b  = (const float*)d_in[17];
    const float* w1      = (const float*)d_in[18];
    const float* b1      = (const float*)d_in[19];
    const float* w2      = (const float*)d_in[20];
    const float* b2      = (const float*)d_in[21];
    float* out = (float*)d_out;

    int smem_front = 8192 + 8704 + 32*129*4 + 128;   // 33.5 KB
    cudaFuncSetAttribute(front_kernel, cudaFuncAttributeMaxDynamicSharedMemorySize, smem_front);

    prep_kernel<<<(NLAY*Hd*Hd + 255)/256, 256>>>(enc_w, dec_w, w1, w2);
    front_kernel<<<1024, 512, smem_front>>>(x, enc_b, norm_w, norm_b,
                                            lam_re, lam_im, p_re, p_im,
                                            b_re, b_im, c_re, c_im, logstep);
    for (int i = 0; i < NLAY; i++) {
        conv_kernel<<<Bsz*Hd/2, 256>>>(dvec + i*Hd, i);
        int last = (i == NLAY-1);
        mlp_kernel<<<ROWS/64, 512>>>(b1 + i*Hd, b2 + i*Hd,
                                     norm_w + (last ? 0 : (i+1)*Hd),
                                     norm_b + (last ? 0 : (i+1)*Hd),
                                     dec_b, out,
                                     i, last ? 0 : 1);
    }
}